// round 7
// baseline (speedup 1.0000x reference)
#include <cuda_runtime.h>
#include <cuda_fp16.h>
#include <cuda_bf16.h>
#include <stdint.h>

#define SDIM 2048
#define DDIM 64
#define TQ 32
#define NTHREADS 512
#define SCH 2088            // sc row stride (u16)
#define SCW 1044            // sc row stride (u32)

// smem byte offsets
#define OFF_SC    0                  // 32*2088*2 = 133632
#define OFF_QS    133632             // 8192
#define OFF_SLOT  141824             // 4 slots * 16384 = 65536
#define OFF_SSUM  207360             // 1024
#define OFF_SINV  208384             // 128
#define OFF_MBAR  208512             // 4*8
#define SMEM_BYTES 208576

// pre-converted chunk-blocked swizzled images: [head][chunk 32][part hi/lo][2048 u32]
__device__ __align__(16) uint32_t g_k[64u * 32u * 2u * 2048u];   // bf16 hi/lo
__device__ __align__(16) uint32_t g_v[64u * 32u * 2u * 2048u];   // fp16 hi/lo, [d][key]

__device__ __forceinline__ void mma16816(float c[4], const uint32_t a[4], const uint32_t b[2]) {
    asm volatile(
        "mma.sync.aligned.m16n8k16.row.col.f32.bf16.bf16.f32 "
        "{%0,%1,%2,%3}, {%4,%5,%6,%7}, {%8,%9}, {%0,%1,%2,%3};\n"
        : "+f"(c[0]), "+f"(c[1]), "+f"(c[2]), "+f"(c[3])
        : "r"(a[0]), "r"(a[1]), "r"(a[2]), "r"(a[3]), "r"(b[0]), "r"(b[1]));
}
__device__ __forceinline__ void mma16808h(float c[4], uint32_t a0, uint32_t a1, uint32_t b0) {
    asm volatile(
        "mma.sync.aligned.m16n8k8.row.col.f32.f16.f16.f32 "
        "{%0,%1,%2,%3}, {%4,%5}, {%6}, {%0,%1,%2,%3};\n"
        : "+f"(c[0]), "+f"(c[1]), "+f"(c[2]), "+f"(c[3])
        : "r"(a0), "r"(a1), "r"(b0));
}

__device__ __forceinline__ void split2(float x, float y, uint32_t &hi, uint32_t &lo) {
    __nv_bfloat16 hx = __float2bfloat16(x);
    __nv_bfloat16 hy = __float2bfloat16(y);
    float rx = x - __bfloat162float(hx);
    float ry = y - __bfloat162float(hy);
    hi = ((uint32_t)__bfloat16_as_ushort(hy) << 16) | (uint32_t)__bfloat16_as_ushort(hx);
    lo = ((uint32_t)__bfloat16_as_ushort(__float2bfloat16(ry)) << 16) |
          (uint32_t)__bfloat16_as_ushort(__float2bfloat16(rx));
}
__device__ __forceinline__ void split1h(float x, uint16_t &h, uint16_t &l) {
    __half hx = __float2half_rn(x);
    h = __half_as_ushort(hx);
    l = __half_as_ushort(__float2half_rn(x - __half2float(hx)));
}

__device__ __forceinline__ uint32_t s2u(const void* p) {
    return (uint32_t)__cvta_generic_to_shared(p);
}
__device__ __forceinline__ void bulk_cp(uint32_t dst, const void* src, uint32_t bytes, uint32_t mbar) {
    asm volatile(
        "cp.async.bulk.shared::cluster.global.mbarrier::complete_tx::bytes [%0], [%1], %2, [%3];"
        :: "r"(dst), "l"(src), "r"(bytes), "r"(mbar) : "memory");
}
#define MBAR_INIT(mb, n) \
    asm volatile("mbarrier.init.shared.b64 [%0], %1;" :: "r"(mb), "r"(n) : "memory")
#define MBAR_EXPECT(mb, tx) \
    asm volatile("mbarrier.arrive.expect_tx.shared.b64 _, [%0], %1;" :: "r"(mb), "r"(tx) : "memory")
__device__ __forceinline__ void mbar_wait(uint32_t mb, uint32_t parity) {
    asm volatile(
        "{\n\t.reg .pred P;\n\t"
        "W_%=:\n\t"
        "mbarrier.try_wait.parity.acquire.cta.shared::cta.b64 P, [%0], %1, 0x989680;\n\t"
        "@P bra.uni D_%=;\n\t"
        "bra.uni W_%=;\n\t"
        "D_%=:\n\t}"
        :: "r"(mb), "r"(parity) : "memory");
}

// phase-stream address: [K_A nA][V_A nA][K_B nB][V_B nB], chunk index is absolute key block
__device__ __forceinline__ const uint32_t* chunk_src(
    int g, int nA, int nB, const uint32_t* kimg, const uint32_t* vimg) {
    int c; const uint32_t* base;
    if (g < nA)            { c = g;                base = kimg; }
    else if (g < 2*nA)     { c = g - nA;           base = vimg; }
    else if (g < 2*nA+nB)  { c = g - 2*nA;         base = kimg; }
    else                   { c = g - 2*nA - nB;    base = vimg; }
    return base + (size_t)c * 4096;
}

// ---------------- pre-convert ----------------
__global__ void conv_k_kernel(const float* __restrict__ kg) {
    int idx = blockIdx.x * blockDim.x + threadIdx.x;
    float4 v = ((const float4*)kg)[idx];
    int kgl = idx >> 4;
    int d4  = (idx & 15) * 4;
    int head = kgl >> 11, key = kgl & 2047;
    int chunk = key >> 6, k6 = key & 63;
    uint32_t h0, l0, h1, l1;
    split2(v.x, v.y, h0, l0);
    split2(v.z, v.w, h1, l1);
    uint32_t wp = (uint32_t)(k6 * 32 + (d4 >> 1)) ^ ((uint32_t)(k6 & 7) << 2);
    size_t base = (size_t)(head * 32 + chunk) * 2 * 2048;
    g_k[base + wp]            = h0;
    g_k[base + wp + 1]        = h1;
    g_k[base + 2048 + wp]     = l0;
    g_k[base + 2048 + wp + 1] = l1;
}

__global__ void conv_v_kernel(const float* __restrict__ vg) {
    __shared__ uint16_t th[64 * 68];
    __shared__ uint16_t tl[64 * 68];
    const int head = blockIdx.y, chunk = blockIdx.x, tid = threadIdx.x;
    const float4* src = (const float4*)(vg + ((size_t)head * SDIM + chunk * 64) * DDIM);
    #pragma unroll
    for (int rep = 0; rep < 4; ++rep) {
        int lin = tid + rep * 256;
        int key = lin >> 4, d4 = (lin & 15) * 4;
        float4 v = src[lin];
        uint16_t h, l;
        split1h(v.x, h, l); th[(d4 + 0) * 68 + key] = h; tl[(d4 + 0) * 68 + key] = l;
        split1h(v.y, h, l); th[(d4 + 1) * 68 + key] = h; tl[(d4 + 1) * 68 + key] = l;
        split1h(v.z, h, l); th[(d4 + 2) * 68 + key] = h; tl[(d4 + 2) * 68 + key] = l;
        split1h(v.w, h, l); th[(d4 + 3) * 68 + key] = h; tl[(d4 + 3) * 68 + key] = l;
    }
    __syncthreads();
    size_t base = (size_t)(head * 32 + chunk) * 2 * 2048;
    #pragma unroll
    for (int rep = 0; rep < 8; ++rep) {
        int lin = tid + rep * 256;
        int d = lin >> 5, kp = lin & 31;
        uint32_t hi = (uint32_t)th[d * 68 + kp * 2] | ((uint32_t)th[d * 68 + kp * 2 + 1] << 16);
        uint32_t lo = (uint32_t)tl[d * 68 + kp * 2] | ((uint32_t)tl[d * 68 + kp * 2 + 1] << 16);
        uint32_t wp = (uint32_t)(d * 32) + ((uint32_t)kp ^ ((uint32_t)(d & 7) << 2));
        g_v[base + wp]        = hi;
        g_v[base + 2048 + wp] = lo;
    }
}

// ---------------- fused attention: paired tiles, 2-pass per tile ----------------
__global__ __launch_bounds__(NTHREADS, 1)
void attn_kernel(const float* __restrict__ qg, float* __restrict__ outg,
                 float* __restrict__ attng)
{
    extern __shared__ char sm[];
    uint16_t* sc   = (uint16_t*)(sm + OFF_SC);
    uint32_t* scw  = (uint32_t*)(sm + OFF_SC);
    float*    qs   = (float*)(sm + OFF_QS);
    uint32_t* slots= (uint32_t*)(sm + OFF_SLOT);
    float*    ssum = (float*)(sm + OFF_SSUM);
    float*    sinv = (float*)(sm + OFF_SINV);

    const int bh = blockIdx.y;
    const int pr = blockIdx.x;                   // pair id
    const int tid = threadIdx.x, lane = tid & 31, wid = tid >> 5;
    const int w7 = wid & 7, rbase = (wid >= 8) ? 16 : 0;
    const int r4 = lane >> 2, l3 = lane & 3, c0 = l3 * 2;
    const uint32_t xm = (uint32_t)(lane >> 2) << 2;

    const size_t headoff = (size_t)bh * SDIM * DDIM;
    const uint32_t* kimg = g_k + (size_t)bh * 32 * 4096;
    const uint32_t* vimg = g_v + (size_t)bh * 32 * 4096;

    const int qbA = pr * TQ, qbB = (63 - pr) * TQ;
    const int nA = (qbA + TQ + 63) >> 6, nB = (qbB + TQ + 63) >> 6;
    const int T = 2 * (nA + nB);

    const uint32_t mbb = s2u(sm + OFF_MBAR);
    if (tid == 0) {
        #pragma unroll
        for (int s = 0; s < 4; ++s) MBAR_INIT(mbb + 8 * s, 1);
    }
    __syncthreads();
    if (tid == 0) {
        #pragma unroll
        for (int gg = 0; gg < 3; ++gg) {    // T >= 66 always
            MBAR_EXPECT(mbb + 8 * gg, 16384);
            bulk_cp(s2u(slots + gg * 4096), chunk_src(gg, nA, nB, kimg, vimg),
                    16384, mbb + 8 * gg);
        }
    }

    int g = 0;
    #pragma unroll 1
    for (int t = 0; t < 2; ++t) {
        const int qbase = t ? qbB : qbA;
        const int n     = t ? nB  : nA;
        const int cendC = n * 64;

        __syncthreads();                       // everyone done with prev tile
        for (int i = tid; i < TQ * DDIM; i += NTHREADS)
            qs[i] = qg[headoff + (size_t)qbase * DDIM + i] * 0.125f;
        __syncthreads();

        // Q A-fragments (bf16 hi/lo)
        uint32_t aqh[4][4], aql[4][4];
        #pragma unroll
        for (int ks = 0; ks < 4; ++ks) {
            const float* q0 = qs + (rbase + r4) * DDIM + ks * 16;
            const float* q1 = q0 + 8 * DDIM;
            split2(q0[c0],     q0[c0 + 1], aqh[ks][0], aql[ks][0]);
            split2(q1[c0],     q1[c0 + 1], aqh[ks][1], aql[ks][1]);
            split2(q0[c0 + 8], q0[c0 + 9], aqh[ks][2], aql[ks][2]);
            split2(q1[c0 + 8], q1[c0 + 9], aqh[ks][3], aql[ks][3]);
        }

        // ---------------- pass 1: QK + exp + sums + sc ----------------
        float s0 = 0.f, s1 = 0.f;
        const int row0 = qbase + rbase + r4, row1 = row0 + 8;
        const int kwb  = (w7 * 8 + (lane >> 2)) * 32;

        #pragma unroll 1
        for (int c = 0; c < n; ++c, ++g) {
            __syncthreads();
            if (tid == 0 && g + 3 < T) {
                int s = (g + 3) & 3;
                MBAR_EXPECT(mbb + 8 * s, 16384);
                bulk_cp(s2u(slots + s * 4096), chunk_src(g + 3, nA, nB, kimg, vimg),
                        16384, mbb + 8 * s);
            }
            mbar_wait(mbb + 8 * (g & 3), (uint32_t)((g >> 2) & 1));

            const uint32_t* kh = slots + (g & 3) * 4096;
            const uint32_t* kl = kh + 2048;
            float a0[4] = {0,0,0,0}, a1[4] = {0,0,0,0};
            float a2[4] = {0,0,0,0}, a3[4] = {0,0,0,0};
            #define QKS(ACC, KS) { \
                uint32_t i0 = kwb + (((uint32_t)((KS)*8 + l3))     ^ xm); \
                uint32_t i1 = kwb + (((uint32_t)((KS)*8 + l3 + 4)) ^ xm); \
                uint32_t bh2[2] = {kh[i0], kh[i1]}; \
                uint32_t bl2[2] = {kl[i0], kl[i1]}; \
                mma16816(ACC, aqh[KS], bh2); \
                mma16816(ACC, aql[KS], bh2); \
                mma16816(ACC, aqh[KS], bl2); }
            QKS(a0, 0) QKS(a1, 1) QKS(a2, 2) QKS(a3, 3)
            #undef QKS

            const float acc0 = (a0[0] + a1[0]) + (a2[0] + a3[0]);
            const float acc1 = (a0[1] + a1[1]) + (a2[1] + a3[1]);
            const float acc2 = (a0[2] + a1[2]) + (a2[2] + a3[2]);
            const float acc3 = (a0[3] + a1[3]) + (a2[3] + a3[3]);

            const int col = c * 64 + w7 * 8 + c0;
            float p0 = (col     <= row0) ? __expf(acc0) : 0.f;
            float p1 = (col + 1 <= row0) ? __expf(acc1) : 0.f;
            float p2 = (col     <= row1) ? __expf(acc2) : 0.f;
            float p3 = (col + 1 <= row1) ? __expf(acc3) : 0.f;
            s0 += p0 + p1;
            s1 += p2 + p3;

            __half2 h01 = __floats2half2_rn(p0, p1);
            __half2 h23 = __floats2half2_rn(p2, p3);
            scw[(rbase + r4) * SCW     + (col >> 1)] = *(uint32_t*)&h01;
            scw[(rbase + r4 + 8) * SCW + (col >> 1)] = *(uint32_t*)&h23;
        }

        // ---------------- row sums -> sinv ----------------
        s0 += __shfl_xor_sync(0xffffffffu, s0, 1);
        s0 += __shfl_xor_sync(0xffffffffu, s0, 2);
        s1 += __shfl_xor_sync(0xffffffffu, s1, 1);
        s1 += __shfl_xor_sync(0xffffffffu, s1, 2);
        if (l3 == 0) {
            ssum[(rbase + r4) * 8 + w7]     = s0;
            ssum[(rbase + r4 + 8) * 8 + w7] = s1;
        }
        __syncthreads();
        if (tid < TQ) {
            float s = 0.f;
            #pragma unroll
            for (int w = 0; w < 8; ++w) s += ssum[tid * 8 + w];
            sinv[tid] = 1.0f / s;
        }
        __syncthreads();

        // ---------------- pass 2: PV (fp16) + interleaved attn write ----------------
        float oc[4] = {0.f, 0.f, 0.f, 0.f};
        const int dloc = w7 * 8 + (lane >> 2);
        const float invr = sinv[tid >> 4];
        float* arow = attng ? attng + ((size_t)bh * SDIM + qbase + (tid >> 4)) * SDIM
                            : (float*)0;

        #pragma unroll 1
        for (int c = 0; c < n; ++c, ++g) {
            __syncthreads();
            if (tid == 0 && g + 3 < T) {
                int s = (g + 3) & 3;
                MBAR_EXPECT(mbb + 8 * s, 16384);
                bulk_cp(s2u(slots + s * 4096), chunk_src(g + 3, nA, nB, kimg, vimg),
                        16384, mbb + 8 * s);
            }
            mbar_wait(mbb + 8 * (g & 3), (uint32_t)((g >> 2) & 1));

            const uint32_t* vh = slots + (g & 3) * 4096;
            const int cb2 = c * 32;
            #pragma unroll
            for (int kg = 0; kg < 8; ++kg) {
                uint32_t pa0 = scw[(rbase + r4) * SCW     + cb2 + kg * 4 + l3];
                uint32_t pa1 = scw[(rbase + r4 + 8) * SCW + cb2 + kg * 4 + l3];
                uint32_t vi = (uint32_t)(dloc * 32) + (((uint32_t)(kg * 4 + l3)) ^ xm);
                mma16808h(oc, pa0, pa1, vh[vi]);
                mma16808h(oc, pa0, pa1, vh[2048 + vi]);
            }

            if (arow) {
                const int jc = c * 64 + (tid & 15) * 4;
                uint2 pk = *(const uint2*)(sc + (tid >> 4) * SCH + jc);
                float2 fa = __half22float2(*(__half2*)&pk.x);
                float2 fb = __half22float2(*(__half2*)&pk.y);
                __stcs((float4*)(arow + jc),
                       make_float4(fa.x * invr, fa.y * invr, fb.x * invr, fb.y * invr));
            }
        }

        // attn tail zeros (cols >= cendC)
        if (arow) {
            for (int j = cendC + (tid & 15) * 4; j < SDIM; j += 64)
                __stcs((float4*)(arow + j), make_float4(0.f, 0.f, 0.f, 0.f));
        }

        // output write (warp-owned 16x8 block, no reduction needed)
        {
            const float sv0 = sinv[rbase + r4], sv1 = sinv[rbase + r4 + 8];
            float* orow = outg + headoff + (size_t)(qbase + rbase + r4) * DDIM;
            const int dc = w7 * 8 + c0;
            *(float2*)(orow + dc)            = make_float2(oc[0] * sv0, oc[1] * sv0);
            *(float2*)(orow + 8 * DDIM + dc) = make_float2(oc[2] * sv1, oc[3] * sv1);
        }
    }
}

extern "C" void kernel_launch(void* const* d_in, const int* in_sizes, int n_in,
                              void* d_out, int out_size) {
    const float* q = (const float*)d_in[0];
    const float* k = (const float*)d_in[1];
    const float* v = (const float*)d_in[2];

    float* out = (float*)d_out;
    const long long OUT_E  = 64LL * 2048 * 64;
    const long long ATTN_E = 64LL * 2048 * 2048;
    float* attn = ((long long)out_size >= OUT_E + ATTN_E) ? out + OUT_E : nullptr;

    conv_k_kernel<<<8192, 256>>>(k);
    {
        dim3 g(32, 64);
        conv_v_kernel<<<g, 256>>>(v);
    }

    cudaFuncSetAttribute(attn_kernel,
                         cudaFuncAttributeMaxDynamicSharedMemorySize, SMEM_BYTES);
    dim3 grid(32, 64);   // 32 balanced tile-pairs x 64 heads
    attn_kernel<<<grid, NTHREADS, SMEM_BYTES>>>(q, out, attn);
}

// round 9
// speedup vs baseline: 1.0505x; 1.0505x over previous
#include <cuda_runtime.h>
#include <cuda_fp16.h>
#include <cuda_bf16.h>
#include <stdint.h>

#define SDIM 2048
#define DDIM 64
#define TQ 32
#define NTHREADS 512
#define SCH 2088            // sc row stride (u16)
#define SCW 1044            // sc row stride (u32)

// smem byte offsets
#define OFF_SC    0                  // 32*2088*2 = 133632
#define OFF_QS    133632             // 8192
#define OFF_SLOT  141824             // 4 slots * 16384 = 65536
#define OFF_SSUM  207360             // 1024
#define OFF_SINV  208384             // 128
#define OFF_MBAR  208512             // 4*8
#define SMEM_BYTES 208576

// pre-converted chunk-blocked swizzled images: [head][chunk 32][part hi/lo][2048 u32]
__device__ __align__(16) uint32_t g_k[64u * 32u * 2u * 2048u];   // bf16 hi/lo, [key][d]
__device__ __align__(16) uint32_t g_v[64u * 32u * 2u * 2048u];   // fp16 hi/lo, [d][key]

__device__ __forceinline__ void mma16816(float c[4], const uint32_t a[4], const uint32_t b[2]) {
    asm volatile(
        "mma.sync.aligned.m16n8k16.row.col.f32.bf16.bf16.f32 "
        "{%0,%1,%2,%3}, {%4,%5,%6,%7}, {%8,%9}, {%0,%1,%2,%3};\n"
        : "+f"(c[0]), "+f"(c[1]), "+f"(c[2]), "+f"(c[3])
        : "r"(a[0]), "r"(a[1]), "r"(a[2]), "r"(a[3]), "r"(b[0]), "r"(b[1]));
}
__device__ __forceinline__ void mma16816h(float c[4], const uint32_t a[4], const uint32_t b[2]) {
    asm volatile(
        "mma.sync.aligned.m16n8k16.row.col.f32.f16.f16.f32 "
        "{%0,%1,%2,%3}, {%4,%5,%6,%7}, {%8,%9}, {%0,%1,%2,%3};\n"
        : "+f"(c[0]), "+f"(c[1]), "+f"(c[2]), "+f"(c[3])
        : "r"(a[0]), "r"(a[1]), "r"(a[2]), "r"(a[3]), "r"(b[0]), "r"(b[1]));
}

__device__ __forceinline__ void split2(float x, float y, uint32_t &hi, uint32_t &lo) {
    __nv_bfloat16 hx = __float2bfloat16(x);
    __nv_bfloat16 hy = __float2bfloat16(y);
    float rx = x - __bfloat162float(hx);
    float ry = y - __bfloat162float(hy);
    hi = ((uint32_t)__bfloat16_as_ushort(hy) << 16) | (uint32_t)__bfloat16_as_ushort(hx);
    lo = ((uint32_t)__bfloat16_as_ushort(__float2bfloat16(ry)) << 16) |
          (uint32_t)__bfloat16_as_ushort(__float2bfloat16(rx));
}
__device__ __forceinline__ void split1h(float x, uint16_t &h, uint16_t &l) {
    __half hx = __float2half_rn(x);
    h = __half_as_ushort(hx);
    l = __half_as_ushort(__float2half_rn(x - __half2float(hx)));
}

__device__ __forceinline__ uint32_t s2u(const void* p) {
    return (uint32_t)__cvta_generic_to_shared(p);
}
__device__ __forceinline__ void bulk_cp(uint32_t dst, const void* src, uint32_t bytes, uint32_t mbar) {
    asm volatile(
        "cp.async.bulk.shared::cluster.global.mbarrier::complete_tx::bytes [%0], [%1], %2, [%3];"
        :: "r"(dst), "l"(src), "r"(bytes), "r"(mbar) : "memory");
}
#define MBAR_INIT(mb, n) \
    asm volatile("mbarrier.init.shared.b64 [%0], %1;" :: "r"(mb), "r"(n) : "memory")
#define MBAR_EXPECT(mb, tx) \
    asm volatile("mbarrier.arrive.expect_tx.shared.b64 _, [%0], %1;" :: "r"(mb), "r"(tx) : "memory")
__device__ __forceinline__ void mbar_wait(uint32_t mb, uint32_t parity) {
    asm volatile(
        "{\n\t.reg .pred P;\n\t"
        "W_%=:\n\t"
        "mbarrier.try_wait.parity.acquire.cta.shared::cta.b64 P, [%0], %1, 0x989680;\n\t"
        "@P bra.uni D_%=;\n\t"
        "bra.uni W_%=;\n\t"
        "D_%=:\n\t}"
        :: "r"(mb), "r"(parity) : "memory");
}

// transfer stream: [K_A nA][V_A nA][K_B nB][V_B nB]
__device__ __forceinline__ const uint32_t* chunk_src(
    int g, int nA, int nB, const uint32_t* kimg, const uint32_t* vimg) {
    int c; const uint32_t* base;
    if (g < nA)            { c = g;                base = kimg; }
    else if (g < 2*nA)     { c = g - nA;           base = vimg; }
    else if (g < 2*nA+nB)  { c = g - 2*nA;         base = kimg; }
    else                   { c = g - 2*nA - nB;    base = vimg; }
    return base + (size_t)c * 4096;
}

// ---------------- pre-convert (single kernel: K + V^T) ----------------
__global__ void conv_kernel(const float* __restrict__ kg, const float* __restrict__ vg) {
    __shared__ uint16_t th[64 * 68];
    __shared__ uint16_t tl[64 * 68];
    const int head = blockIdx.y, chunk = blockIdx.x, tid = threadIdx.x;
    const size_t srcoff = ((size_t)head * SDIM + (size_t)chunk * 64) * DDIM;

    // ---- K: [key][d] bf16 hi/lo, direct swizzled store ----
    {
        uint32_t* kb = g_k + (size_t)(head * 32 + chunk) * 4096;
        const float4* ksrc = (const float4*)(kg + srcoff);
        #pragma unroll
        for (int rep = 0; rep < 4; ++rep) {
            int lin = tid + rep * 256;           // 1024 float4
            int k6 = lin >> 4, d4 = (lin & 15) * 4;
            float4 v = ksrc[lin];
            uint32_t h0, l0, h1, l1;
            split2(v.x, v.y, h0, l0);
            split2(v.z, v.w, h1, l1);
            uint32_t wp = (uint32_t)(k6 * 32 + (d4 >> 1)) ^ ((uint32_t)(k6 & 7) << 2);
            kb[wp]            = h0;
            kb[wp + 1]        = h1;
            kb[2048 + wp]     = l0;
            kb[2048 + wp + 1] = l1;
        }
    }

    // ---- V: transpose to [d][key] fp16 hi/lo via smem ----
    {
        const float4* vsrc = (const float4*)(vg + srcoff);
        #pragma unroll
        for (int rep = 0; rep < 4; ++rep) {
            int lin = tid + rep * 256;
            int key = lin >> 4, d4 = (lin & 15) * 4;
            float4 v = vsrc[lin];
            uint16_t h, l;
            split1h(v.x, h, l); th[(d4 + 0) * 68 + key] = h; tl[(d4 + 0) * 68 + key] = l;
            split1h(v.y, h, l); th[(d4 + 1) * 68 + key] = h; tl[(d4 + 1) * 68 + key] = l;
            split1h(v.z, h, l); th[(d4 + 2) * 68 + key] = h; tl[(d4 + 2) * 68 + key] = l;
            split1h(v.w, h, l); th[(d4 + 3) * 68 + key] = h; tl[(d4 + 3) * 68 + key] = l;
        }
        __syncthreads();
        uint32_t* vb = g_v + (size_t)(head * 32 + chunk) * 4096;
        #pragma unroll
        for (int rep = 0; rep < 8; ++rep) {
            int lin = tid + rep * 256;           // 2048 words
            int d = lin >> 5, kp = lin & 31;
            uint32_t hi = (uint32_t)th[d * 68 + kp * 2] | ((uint32_t)th[d * 68 + kp * 2 + 1] << 16);
            uint32_t lo = (uint32_t)tl[d * 68 + kp * 2] | ((uint32_t)tl[d * 68 + kp * 2 + 1] << 16);
            uint32_t wp = (uint32_t)(d * 32) + ((uint32_t)kp ^ ((uint32_t)(d & 7) << 2));
            vb[wp]        = hi;
            vb[2048 + wp] = lo;
        }
    }
}

// ---------------- fused attention: paired tiles, 2-pass per tile ----------------
__global__ __launch_bounds__(NTHREADS, 1)
void attn_kernel(const float* __restrict__ qg, float* __restrict__ outg,
                 float* __restrict__ attng)
{
    extern __shared__ char sm[];
    uint16_t* sc   = (uint16_t*)(sm + OFF_SC);
    uint32_t* scw  = (uint32_t*)(sm + OFF_SC);
    float*    qs   = (float*)(sm + OFF_QS);
    uint32_t* slots= (uint32_t*)(sm + OFF_SLOT);
    float*    ssum = (float*)(sm + OFF_SSUM);
    float*    sinv = (float*)(sm + OFF_SINV);

    const int bh = blockIdx.y;
    const int pr = blockIdx.x;                   // pair id
    const int tid = threadIdx.x, lane = tid & 31, wid = tid >> 5;
    const int w7 = wid & 7, rbase = (wid >= 8) ? 16 : 0;
    const int r4 = lane >> 2, l3 = lane & 3, c0 = l3 * 2;
    const uint32_t xm = (uint32_t)(lane >> 2) << 2;

    const size_t headoff = (size_t)bh * SDIM * DDIM;
    const uint32_t* kimg = g_k + (size_t)bh * 32 * 4096;
    const uint32_t* vimg = g_v + (size_t)bh * 32 * 4096;

    const int qbA = pr * TQ, qbB = (63 - pr) * TQ;
    const int nA = (qbA + TQ + 63) >> 6, nB = (qbB + TQ + 63) >> 6;
    const int T = 2 * (nA + nB);

    const uint32_t mbb = s2u(sm + OFF_MBAR);
    if (tid == 0) {
        #pragma unroll
        for (int s = 0; s < 4; ++s) MBAR_INIT(mbb + 8 * s, 1);
    }
    __syncthreads();
    if (tid == 0) {
        #pragma unroll
        for (int gg = 0; gg < 3; ++gg) {
            MBAR_EXPECT(mbb + 8 * gg, 16384);
            bulk_cp(s2u(slots + gg * 4096), chunk_src(gg, nA, nB, kimg, vimg),
                    16384, mbb + 8 * gg);
        }
    }

    int g = 0;
    #pragma unroll 1
    for (int t = 0; t < 2; ++t) {
        const int qbase = t ? qbB : qbA;
        const int n     = t ? nB  : nA;
        const int cendC = n * 64;

        __syncthreads();
        for (int i = tid; i < TQ * DDIM; i += NTHREADS)
            qs[i] = qg[headoff + (size_t)qbase * DDIM + i] * 0.125f;
        __syncthreads();

        // Q A-fragments (bf16 hi/lo)
        uint32_t aqh[4][4], aql[4][4];
        #pragma unroll
        for (int ks = 0; ks < 4; ++ks) {
            const float* q0 = qs + (rbase + r4) * DDIM + ks * 16;
            const float* q1 = q0 + 8 * DDIM;
            split2(q0[c0],     q0[c0 + 1], aqh[ks][0], aql[ks][0]);
            split2(q1[c0],     q1[c0 + 1], aqh[ks][1], aql[ks][1]);
            split2(q0[c0 + 8], q0[c0 + 9], aqh[ks][2], aql[ks][2]);
            split2(q1[c0 + 8], q1[c0 + 9], aqh[ks][3], aql[ks][3]);
        }

        // ---------------- pass 1: QK + exp + sums + sc ----------------
        float s0 = 0.f, s1 = 0.f;
        const int row0 = qbase + rbase + r4, row1 = row0 + 8;
        const int kwb  = (w7 * 8 + (lane >> 2)) * 32;

        #pragma unroll 1
        for (int c = 0; c < n; ++c, ++g) {
            __syncthreads();
            if (tid == 0 && g + 3 < T) {
                int s = (g + 3) & 3;
                MBAR_EXPECT(mbb + 8 * s, 16384);
                bulk_cp(s2u(slots + s * 4096), chunk_src(g + 3, nA, nB, kimg, vimg),
                        16384, mbb + 8 * s);
            }
            mbar_wait(mbb + 8 * (g & 3), (uint32_t)((g >> 2) & 1));

            const uint32_t* kh = slots + (g & 3) * 4096;
            const uint32_t* kl = kh + 2048;
            float a0[4] = {0,0,0,0}, a1[4] = {0,0,0,0};
            float a2[4] = {0,0,0,0}, a3[4] = {0,0,0,0};
            #define QKS(ACC, KS) { \
                uint32_t i0 = kwb + (((uint32_t)((KS)*8 + l3))     ^ xm); \
                uint32_t i1 = kwb + (((uint32_t)((KS)*8 + l3 + 4)) ^ xm); \
                uint32_t bh2[2] = {kh[i0], kh[i1]}; \
                uint32_t bl2[2] = {kl[i0], kl[i1]}; \
                mma16816(ACC, aqh[KS], bh2); \
                mma16816(ACC, aql[KS], bh2); \
                mma16816(ACC, aqh[KS], bl2); }
            QKS(a0, 0) QKS(a1, 1) QKS(a2, 2) QKS(a3, 3)
            #undef QKS

            const float acc0 = (a0[0] + a1[0]) + (a2[0] + a3[0]);
            const float acc1 = (a0[1] + a1[1]) + (a2[1] + a3[1]);
            const float acc2 = (a0[2] + a1[2]) + (a2[2] + a3[2]);
            const float acc3 = (a0[3] + a1[3]) + (a2[3] + a3[3]);

            const int col = c * 64 + w7 * 8 + c0;
            float p0 = (col     <= row0) ? __expf(acc0) : 0.f;
            float p1 = (col + 1 <= row0) ? __expf(acc1) : 0.f;
            float p2 = (col     <= row1) ? __expf(acc2) : 0.f;
            float p3 = (col + 1 <= row1) ? __expf(acc3) : 0.f;
            s0 += p0 + p1;
            s1 += p2 + p3;

            __half2 h01 = __floats2half2_rn(p0, p1);
            __half2 h23 = __floats2half2_rn(p2, p3);
            scw[(rbase + r4) * SCW     + (col >> 1)] = *(uint32_t*)&h01;
            scw[(rbase + r4 + 8) * SCW + (col >> 1)] = *(uint32_t*)&h23;
        }

        // ---------------- row sums -> sinv ----------------
        s0 += __shfl_xor_sync(0xffffffffu, s0, 1);
        s0 += __shfl_xor_sync(0xffffffffu, s0, 2);
        s1 += __shfl_xor_sync(0xffffffffu, s1, 1);
        s1 += __shfl_xor_sync(0xffffffffu, s1, 2);
        if (l3 == 0) {
            ssum[(rbase + r4) * 8 + w7]     = s0;
            ssum[(rbase + r4 + 8) * 8 + w7] = s1;
        }
        __syncthreads();
        if (tid < TQ) {
            float s = 0.f;
            #pragma unroll
            for (int w = 0; w < 8; ++w) s += ssum[tid * 8 + w];
            sinv[tid] = 1.0f / s;
        }
        __syncthreads();

        // ---------------- pass 2: PV (fp16 k16) + interleaved attn write ----------------
        float oc[4] = {0.f, 0.f, 0.f, 0.f};
        const int dloc = w7 * 8 + (lane >> 2);
        const float invr = sinv[tid >> 4];
        float* arow = attng ? attng + ((size_t)bh * SDIM + qbase + (tid >> 4)) * SDIM
                            : (float*)0;

        #pragma unroll 1
        for (int c = 0; c < n; ++c, ++g) {
            __syncthreads();
            if (tid == 0 && g + 3 < T) {
                int s = (g + 3) & 3;
                MBAR_EXPECT(mbb + 8 * s, 16384);
                bulk_cp(s2u(slots + s * 4096), chunk_src(g + 3, nA, nB, kimg, vimg),
                        16384, mbb + 8 * s);
            }
            mbar_wait(mbb + 8 * (g & 3), (uint32_t)((g >> 2) & 1));

            const uint32_t* vh = slots + (g & 3) * 4096;
            const int cb2 = c * 32;
            #pragma unroll
            for (int kg = 0; kg < 4; ++kg) {
                uint32_t a[4];
                a[0] = scw[(rbase + r4) * SCW     + cb2 + kg * 8 + l3];
                a[1] = scw[(rbase + r4 + 8) * SCW + cb2 + kg * 8 + l3];
                a[2] = scw[(rbase + r4) * SCW     + cb2 + kg * 8 + 4 + l3];
                a[3] = scw[(rbase + r4 + 8) * SCW + cb2 + kg * 8 + 4 + l3];
                uint32_t vi0 = (uint32_t)(dloc * 32) + (((uint32_t)(kg * 8 + l3))     ^ xm);
                uint32_t vi1 = (uint32_t)(dloc * 32) + (((uint32_t)(kg * 8 + 4 + l3)) ^ xm);
                uint32_t bh2[2] = {vh[vi0],        vh[vi1]};
                uint32_t bl2[2] = {vh[2048 + vi0], vh[2048 + vi1]};
                mma16816h(oc, a, bh2);
                mma16816h(oc, a, bl2);
            }

            if (arow) {
                const int jc = c * 64 + (tid & 15) * 4;
                uint2 pk = *(const uint2*)(sc + (tid >> 4) * SCH + jc);
                float2 fa = __half22float2(*(__half2*)&pk.x);
                float2 fb = __half22float2(*(__half2*)&pk.y);
                __stcs((float4*)(arow + jc),
                       make_float4(fa.x * invr, fa.y * invr, fb.x * invr, fb.y * invr));
            }
        }

        // attn tail zeros
        if (arow) {
            for (int j = cendC + (tid & 15) * 4; j < SDIM; j += 64)
                __stcs((float4*)(arow + j), make_float4(0.f, 0.f, 0.f, 0.f));
        }

        // output write (warp-owned 16x8 block)
        {
            const float sv0 = sinv[rbase + r4], sv1 = sinv[rbase + r4 + 8];
            float* orow = outg + headoff + (size_t)(qbase + rbase + r4) * DDIM;
            const int dc = w7 * 8 + c0;
            *(float2*)(orow + dc)            = make_float2(oc[0] * sv0, oc[1] * sv0);
            *(float2*)(orow + 8 * DDIM + dc) = make_float2(oc[2] * sv1, oc[3] * sv1);
        }
    }
}

extern "C" void kernel_launch(void* const* d_in, const int* in_sizes, int n_in,
                              void* d_out, int out_size) {
    const float* q = (const float*)d_in[0];
    const float* k = (const float*)d_in[1];
    const float* v = (const float*)d_in[2];

    float* out = (float*)d_out;
    const long long OUT_E  = 64LL * 2048 * 64;
    const long long ATTN_E = 64LL * 2048 * 2048;
    float* attn = ((long long)out_size >= OUT_E + ATTN_E) ? out + OUT_E : nullptr;

    {
        dim3 g(32, 64);
        conv_kernel<<<g, 256>>>(k, v);
    }

    cudaFuncSetAttribute(attn_kernel,
                         cudaFuncAttributeMaxDynamicSharedMemorySize, SMEM_BYTES);
    dim3 grid(32, 64);   // 32 balanced tile-pairs x 64 heads
    attn_kernel<<<grid, NTHREADS, SMEM_BYTES>>>(q, out, attn);
}

// round 10
// speedup vs baseline: 1.2171x; 1.1586x over previous
#include <cuda_runtime.h>
#include <cuda_fp16.h>
#include <cuda_bf16.h>
#include <stdint.h>

#define SDIM 2048
#define DDIM 64
#define TQ 32
#define NTHREADS 512
#define SCH 2088            // sc row stride (u16)
#define SCW 1044            // sc row stride (u32)

// smem byte offsets
#define OFF_SC    0                  // 32*2088*2 = 133632
#define OFF_QS    133632             // 8192
#define OFF_SLOT  141824             // 4 slots * 16384 = 65536
#define OFF_SSUM  207360             // 1024
#define OFF_SINV  208384             // 128
#define OFF_MBAR  208512             // full[4] then empty[4]
#define SMEM_BYTES 208576

// pre-converted chunk-blocked swizzled images: [head][chunk 32][part hi/lo][2048 u32]
__device__ __align__(16) uint32_t g_k[64u * 32u * 2u * 2048u];   // bf16 hi/lo, [key][d]
__device__ __align__(16) uint32_t g_v[64u * 32u * 2u * 2048u];   // fp16 hi/lo, [d][key]

__device__ __forceinline__ void mma16816(float c[4], const uint32_t a[4], const uint32_t b[2]) {
    asm volatile(
        "mma.sync.aligned.m16n8k16.row.col.f32.bf16.bf16.f32 "
        "{%0,%1,%2,%3}, {%4,%5,%6,%7}, {%8,%9}, {%0,%1,%2,%3};\n"
        : "+f"(c[0]), "+f"(c[1]), "+f"(c[2]), "+f"(c[3])
        : "r"(a[0]), "r"(a[1]), "r"(a[2]), "r"(a[3]), "r"(b[0]), "r"(b[1]));
}
__device__ __forceinline__ void mma16816h(float c[4], const uint32_t a[4], const uint32_t b[2]) {
    asm volatile(
        "mma.sync.aligned.m16n8k16.row.col.f32.f16.f16.f32 "
        "{%0,%1,%2,%3}, {%4,%5,%6,%7}, {%8,%9}, {%0,%1,%2,%3};\n"
        : "+f"(c[0]), "+f"(c[1]), "+f"(c[2]), "+f"(c[3])
        : "r"(a[0]), "r"(a[1]), "r"(a[2]), "r"(a[3]), "r"(b[0]), "r"(b[1]));
}

__device__ __forceinline__ void split2(float x, float y, uint32_t &hi, uint32_t &lo) {
    __nv_bfloat16 hx = __float2bfloat16(x);
    __nv_bfloat16 hy = __float2bfloat16(y);
    float rx = x - __bfloat162float(hx);
    float ry = y - __bfloat162float(hy);
    hi = ((uint32_t)__bfloat16_as_ushort(hy) << 16) | (uint32_t)__bfloat16_as_ushort(hx);
    lo = ((uint32_t)__bfloat16_as_ushort(__float2bfloat16(ry)) << 16) |
          (uint32_t)__bfloat16_as_ushort(__float2bfloat16(rx));
}
__device__ __forceinline__ void split1h(float x, uint16_t &h, uint16_t &l) {
    __half hx = __float2half_rn(x);
    h = __half_as_ushort(hx);
    l = __half_as_ushort(__float2half_rn(x - __half2float(hx)));
}

__device__ __forceinline__ uint32_t s2u(const void* p) {
    return (uint32_t)__cvta_generic_to_shared(p);
}
__device__ __forceinline__ void bulk_cp(uint32_t dst, const void* src, uint32_t bytes, uint32_t mbar) {
    asm volatile(
        "cp.async.bulk.shared::cluster.global.mbarrier::complete_tx::bytes [%0], [%1], %2, [%3];"
        :: "r"(dst), "l"(src), "r"(bytes), "r"(mbar) : "memory");
}
#define MBAR_INIT(mb, n) \
    asm volatile("mbarrier.init.shared.b64 [%0], %1;" :: "r"(mb), "r"(n) : "memory")
#define MBAR_EXPECT(mb, tx) \
    asm volatile("mbarrier.arrive.expect_tx.shared.b64 _, [%0], %1;" :: "r"(mb), "r"(tx) : "memory")
#define MBAR_ARRIVE(mb) \
    asm volatile("mbarrier.arrive.shared.b64 _, [%0];" :: "r"(mb) : "memory")
__device__ __forceinline__ void mbar_wait(uint32_t mb, uint32_t parity) {
    asm volatile(
        "{\n\t.reg .pred P;\n\t"
        "W_%=:\n\t"
        "mbarrier.try_wait.parity.acquire.cta.shared::cta.b64 P, [%0], %1, 0x989680;\n\t"
        "@P bra.uni D_%=;\n\t"
        "bra.uni W_%=;\n\t"
        "D_%=:\n\t}"
        :: "r"(mb), "r"(parity) : "memory");
}
#define HBAR(h) asm volatile("bar.sync %0, %1;" :: "r"((h) + 1), "r"(256) : "memory")

// transfer stream: [K_A nA][V_A nA][K_B nB][V_B nB]
__device__ __forceinline__ const uint32_t* chunk_src(
    int g, int nA, int nB, const uint32_t* kimg, const uint32_t* vimg) {
    int c; const uint32_t* base;
    if (g < nA)            { c = g;                base = kimg; }
    else if (g < 2*nA)     { c = g - nA;           base = vimg; }
    else if (g < 2*nA+nB)  { c = g - 2*nA;         base = kimg; }
    else                   { c = g - 2*nA - nB;    base = vimg; }
    return base + (size_t)c * 4096;
}

// ---------------- pre-convert (K + V^T, single kernel) ----------------
__global__ void conv_kernel(const float* __restrict__ kg, const float* __restrict__ vg) {
    __shared__ uint16_t th[64 * 68];
    __shared__ uint16_t tl[64 * 68];
    const int head = blockIdx.y, chunk = blockIdx.x, tid = threadIdx.x;
    const size_t srcoff = ((size_t)head * SDIM + (size_t)chunk * 64) * DDIM;

    {   // K: [key][d] bf16 hi/lo
        uint32_t* kb = g_k + (size_t)(head * 32 + chunk) * 4096;
        const float4* ksrc = (const float4*)(kg + srcoff);
        #pragma unroll
        for (int rep = 0; rep < 4; ++rep) {
            int lin = tid + rep * 256;
            int k6 = lin >> 4, d4 = (lin & 15) * 4;
            float4 v = ksrc[lin];
            uint32_t h0, l0, h1, l1;
            split2(v.x, v.y, h0, l0);
            split2(v.z, v.w, h1, l1);
            uint32_t wp = (uint32_t)(k6 * 32 + (d4 >> 1)) ^ ((uint32_t)(k6 & 7) << 2);
            kb[wp] = h0; kb[wp + 1] = h1;
            kb[2048 + wp] = l0; kb[2048 + wp + 1] = l1;
        }
    }
    {   // V: transpose to [d][key] fp16 hi/lo
        const float4* vsrc = (const float4*)(vg + srcoff);
        #pragma unroll
        for (int rep = 0; rep < 4; ++rep) {
            int lin = tid + rep * 256;
            int key = lin >> 4, d4 = (lin & 15) * 4;
            float4 v = vsrc[lin];
            uint16_t h, l;
            split1h(v.x, h, l); th[(d4 + 0) * 68 + key] = h; tl[(d4 + 0) * 68 + key] = l;
            split1h(v.y, h, l); th[(d4 + 1) * 68 + key] = h; tl[(d4 + 1) * 68 + key] = l;
            split1h(v.z, h, l); th[(d4 + 2) * 68 + key] = h; tl[(d4 + 2) * 68 + key] = l;
            split1h(v.w, h, l); th[(d4 + 3) * 68 + key] = h; tl[(d4 + 3) * 68 + key] = l;
        }
        __syncthreads();
        uint32_t* vb = g_v + (size_t)(head * 32 + chunk) * 4096;
        #pragma unroll
        for (int rep = 0; rep < 8; ++rep) {
            int lin = tid + rep * 256;
            int d = lin >> 5, kp = lin & 31;
            uint32_t hi = (uint32_t)th[d * 68 + kp * 2] | ((uint32_t)th[d * 68 + kp * 2 + 1] << 16);
            uint32_t lo = (uint32_t)tl[d * 68 + kp * 2] | ((uint32_t)tl[d * 68 + kp * 2 + 1] << 16);
            uint32_t wp = (uint32_t)(d * 32) + ((uint32_t)kp ^ ((uint32_t)(d & 7) << 2));
            vb[wp] = hi; vb[2048 + wp] = lo;
        }
    }
}

// ---------------- fused attention: async slots, independent halves ----------------
__global__ __launch_bounds__(NTHREADS, 1)
void attn_kernel(const float* __restrict__ qg, float* __restrict__ outg,
                 float* __restrict__ attng)
{
    extern __shared__ char sm[];
    uint16_t* sc   = (uint16_t*)(sm + OFF_SC);
    uint32_t* scw  = (uint32_t*)(sm + OFF_SC);
    float*    qs   = (float*)(sm + OFF_QS);
    uint32_t* slots= (uint32_t*)(sm + OFF_SLOT);
    float*    ssum = (float*)(sm + OFF_SSUM);
    float*    sinv = (float*)(sm + OFF_SINV);

    const int bh = blockIdx.y;
    const int pr = blockIdx.x;
    const int tid = threadIdx.x, lane = tid & 31, wid = tid >> 5;
    const int w7 = wid & 7, hh = wid >> 3, rbase = hh * 16;
    const int tid_h = tid & 255;
    const int r4 = lane >> 2, l3 = lane & 3, c0 = l3 * 2;
    const uint32_t xm = (uint32_t)(lane >> 2) << 2;

    const size_t headoff = (size_t)bh * SDIM * DDIM;
    const uint32_t* kimg = g_k + (size_t)bh * 32 * 4096;
    const uint32_t* vimg = g_v + (size_t)bh * 32 * 4096;

    const int qbA = pr * TQ, qbB = (63 - pr) * TQ;
    const int nA = (qbA + TQ + 63) >> 6, nB = (qbB + TQ + 63) >> 6;
    const int T = 2 * (nA + nB);

    const uint32_t mbF = s2u(sm + OFF_MBAR);       // full[4]
    const uint32_t mbE = mbF + 32;                 // empty[4]
    if (tid == 0) {
        #pragma unroll
        for (int s = 0; s < 4; ++s) { MBAR_INIT(mbF + 8 * s, 1); MBAR_INIT(mbE + 8 * s, 16); }
    }
    __syncthreads();
    if (tid == 0) {
        #pragma unroll
        for (int j = 0; j < 3; ++j) {
            MBAR_EXPECT(mbF + 8 * j, 16384);
            bulk_cp(s2u(slots + j * 4096), chunk_src(j, nA, nB, kimg, vimg),
                    16384, mbF + 8 * j);
        }
    }

    // tid0: issue transfer g+3 (waits empty of g-1 when needed)
    auto issue_next = [&](int g) {
        int j = g + 3;
        if (j >= T) return;
        int s = j & 3;
        if (j >= 4) mbar_wait(mbE + 8 * s, (uint32_t)(((j >> 2) - 1) & 1));
        MBAR_EXPECT(mbF + 8 * s, 16384);
        bulk_cp(s2u(slots + s * 4096), chunk_src(j, nA, nB, kimg, vimg), 16384, mbF + 8 * s);
    };

    int g = 0;
    #pragma unroll 1
    for (int t = 0; t < 2; ++t) {
        const int qbase = t ? qbB : qbA;
        const int n     = t ? nB  : nA;
        const int cendC = n * 64;

        // ---- stage q rows of own half ----
        {
            int rl = tid_h >> 4, dg = (tid_h & 15) * 4;
            float4 v = *(const float4*)(qg + headoff + (size_t)(qbase + rbase + rl) * DDIM + dg);
            *(float4*)(qs + (rbase + rl) * DDIM + dg) =
                make_float4(v.x * 0.125f, v.y * 0.125f, v.z * 0.125f, v.w * 0.125f);
        }
        HBAR(hh);

        // Q A-fragments (bf16 hi/lo), own-half rows
        uint32_t aqh[4][4], aql[4][4];
        #pragma unroll
        for (int ks = 0; ks < 4; ++ks) {
            const float* q0 = qs + (rbase + r4) * DDIM + ks * 16;
            const float* q1 = q0 + 8 * DDIM;
            split2(q0[c0],     q0[c0 + 1], aqh[ks][0], aql[ks][0]);
            split2(q1[c0],     q1[c0 + 1], aqh[ks][1], aql[ks][1]);
            split2(q0[c0 + 8], q0[c0 + 9], aqh[ks][2], aql[ks][2]);
            split2(q1[c0 + 8], q1[c0 + 9], aqh[ks][3], aql[ks][3]);
        }

        // ---------------- pass 1: QK + exp + sums + sc ----------------
        float s0 = 0.f, s1 = 0.f;
        const int row0 = qbase + rbase + r4, row1 = row0 + 8;
        const int kwb  = (w7 * 8 + (lane >> 2)) * 32;

        #pragma unroll 1
        for (int c = 0; c < n; ++c, ++g) {
            if (tid == 0) issue_next(g);
            mbar_wait(mbF + 8 * (g & 3), (uint32_t)((g >> 2) & 1));

            const uint32_t* kh = slots + (g & 3) * 4096;
            const uint32_t* kl = kh + 2048;
            float a0[4] = {0,0,0,0}, a1[4] = {0,0,0,0};
            float a2[4] = {0,0,0,0}, a3[4] = {0,0,0,0};
            #define QKS(ACC, KS) { \
                uint32_t i0 = kwb + (((uint32_t)((KS)*8 + l3))     ^ xm); \
                uint32_t i1 = kwb + (((uint32_t)((KS)*8 + l3 + 4)) ^ xm); \
                uint32_t bh2[2] = {kh[i0], kh[i1]}; \
                uint32_t bl2[2] = {kl[i0], kl[i1]}; \
                mma16816(ACC, aqh[KS], bh2); \
                mma16816(ACC, aql[KS], bh2); \
                mma16816(ACC, aqh[KS], bl2); }
            QKS(a0, 0) QKS(a1, 1) QKS(a2, 2) QKS(a3, 3)
            #undef QKS

            __syncwarp();
            if (lane == 0) MBAR_ARRIVE(mbE + 8 * (g & 3));

            const float acc0 = (a0[0] + a1[0]) + (a2[0] + a3[0]);
            const float acc1 = (a0[1] + a1[1]) + (a2[1] + a3[1]);
            const float acc2 = (a0[2] + a1[2]) + (a2[2] + a3[2]);
            const float acc3 = (a0[3] + a1[3]) + (a2[3] + a3[3]);

            const int col = c * 64 + w7 * 8 + c0;
            float p0 = (col     <= row0) ? __expf(acc0) : 0.f;
            float p1 = (col + 1 <= row0) ? __expf(acc1) : 0.f;
            float p2 = (col     <= row1) ? __expf(acc2) : 0.f;
            float p3 = (col + 1 <= row1) ? __expf(acc3) : 0.f;
            s0 += p0 + p1;
            s1 += p2 + p3;

            __half2 h01 = __floats2half2_rn(p0, p1);
            __half2 h23 = __floats2half2_rn(p2, p3);
            scw[(rbase + r4) * SCW     + (col >> 1)] = *(uint32_t*)&h01;
            scw[(rbase + r4 + 8) * SCW + (col >> 1)] = *(uint32_t*)&h23;
        }

        // ---------------- row sums -> sinv (per half) ----------------
        s0 += __shfl_xor_sync(0xffffffffu, s0, 1);
        s0 += __shfl_xor_sync(0xffffffffu, s0, 2);
        s1 += __shfl_xor_sync(0xffffffffu, s1, 1);
        s1 += __shfl_xor_sync(0xffffffffu, s1, 2);
        if (l3 == 0) {
            ssum[(rbase + r4) * 8 + w7]     = s0;
            ssum[(rbase + r4 + 8) * 8 + w7] = s1;
        }
        HBAR(hh);
        if (tid_h < 16) {
            float s = 0.f;
            #pragma unroll
            for (int w = 0; w < 8; ++w) s += ssum[(rbase + tid_h) * 8 + w];
            sinv[rbase + tid_h] = 1.0f / s;
        }
        HBAR(hh);

        // ---------------- pass 2: PV (fp16 k16) + interleaved attn write ----------------
        float oc[4] = {0.f, 0.f, 0.f, 0.f};
        const int dloc = w7 * 8 + (lane >> 2);
        const int arown = rbase + (tid_h >> 4);
        const float invr = sinv[arown];
        float* arow = attng ? attng + ((size_t)bh * SDIM + qbase + arown) * SDIM : (float*)0;

        #pragma unroll 1
        for (int c = 0; c < n; ++c, ++g) {
            if (tid == 0) issue_next(g);
            mbar_wait(mbF + 8 * (g & 3), (uint32_t)((g >> 2) & 1));

            const uint32_t* vh = slots + (g & 3) * 4096;
            const int cb2 = c * 32;
            #pragma unroll
            for (int kg = 0; kg < 4; ++kg) {
                uint32_t a[4];
                a[0] = scw[(rbase + r4) * SCW     + cb2 + kg * 8 + l3];
                a[1] = scw[(rbase + r4 + 8) * SCW + cb2 + kg * 8 + l3];
                a[2] = scw[(rbase + r4) * SCW     + cb2 + kg * 8 + 4 + l3];
                a[3] = scw[(rbase + r4 + 8) * SCW + cb2 + kg * 8 + 4 + l3];
                uint32_t vi0 = (uint32_t)(dloc * 32) + (((uint32_t)(kg * 8 + l3))     ^ xm);
                uint32_t vi1 = (uint32_t)(dloc * 32) + (((uint32_t)(kg * 8 + 4 + l3)) ^ xm);
                uint32_t bh2[2] = {vh[vi0],        vh[vi1]};
                uint32_t bl2[2] = {vh[2048 + vi0], vh[2048 + vi1]};
                mma16816h(oc, a, bh2);
                mma16816h(oc, a, bl2);
            }

            __syncwarp();
            if (lane == 0) MBAR_ARRIVE(mbE + 8 * (g & 3));

            if (arow) {
                const int jc = c * 64 + (tid_h & 15) * 4;
                uint2 pk = *(const uint2*)(sc + arown * SCH + jc);
                float2 fa = __half22float2(*(__half2*)&pk.x);
                float2 fb = __half22float2(*(__half2*)&pk.y);
                __stcs((float4*)(arow + jc),
                       make_float4(fa.x * invr, fa.y * invr, fb.x * invr, fb.y * invr));
            }
        }

        // attn tail zeros (own-half rows)
        if (arow) {
            for (int j = cendC + (tid_h & 15) * 4; j < SDIM; j += 64)
                __stcs((float4*)(arow + j), make_float4(0.f, 0.f, 0.f, 0.f));
        }

        // output write (warp-owned 16x8 block, own half)
        {
            const float sv0 = sinv[rbase + r4], sv1 = sinv[rbase + r4 + 8];
            float* orow = outg + headoff + (size_t)(qbase + rbase + r4) * DDIM;
            const int dc = w7 * 8 + c0;
            *(float2*)(orow + dc)            = make_float2(oc[0] * sv0, oc[1] * sv0);
            *(float2*)(orow + 8 * DDIM + dc) = make_float2(oc[2] * sv1, oc[3] * sv1);
        }
        HBAR(hh);   // own half fully done with sc/qs before next tile overwrites
    }
}

extern "C" void kernel_launch(void* const* d_in, const int* in_sizes, int n_in,
                              void* d_out, int out_size) {
    const float* q = (const float*)d_in[0];
    const float* k = (const float*)d_in[1];
    const float* v = (const float*)d_in[2];

    float* out = (float*)d_out;
    const long long OUT_E  = 64LL * 2048 * 64;
    const long long ATTN_E = 64LL * 2048 * 2048;
    float* attn = ((long long)out_size >= OUT_E + ATTN_E) ? out + OUT_E : nullptr;

    {
        dim3 g(32, 64);
        conv_kernel<<<g, 256>>>(k, v);
    }

    cudaFuncSetAttribute(attn_kernel,
                         cudaFuncAttributeMaxDynamicSharedMemorySize, SMEM_BYTES);
    dim3 grid(32, 64);
    attn_kernel<<<grid, NTHREADS, SMEM_BYTES>>>(q, out, attn);
}

// round 11
// speedup vs baseline: 1.2633x; 1.0380x over previous
#include <cuda_runtime.h>
#include <cuda_fp16.h>
#include <cuda_bf16.h>
#include <stdint.h>

#define SDIM 2048
#define DDIM 64
#define TQ 32
#define NTHREADS 512
#define SCH 2088            // sc row stride (u16)
#define SCW 1044            // sc row stride (u32)

// smem byte offsets
#define OFF_SC    0                  // 32*2088*2 = 133632
#define OFF_QS    133632             // 8192
#define OFF_SLOT  141824             // 4 slots * 16384 = 65536
#define OFF_SSUM  207360             // 1024
#define OFF_SINV  208384             // 128
#define OFF_MBAR  208512             // full[4] then empty[4]
#define SMEM_BYTES 208576

// pre-converted chunk-blocked swizzled images
__device__ __align__(16) uint32_t g_k[64u * 32u * 2048u];        // fp16 single, [key][d]
__device__ __align__(16) uint32_t g_v[64u * 32u * 2u * 2048u];   // fp16 hi/lo, [d][key]

__device__ __forceinline__ void mma16816h(float c[4], const uint32_t a[4], const uint32_t b[2]) {
    asm volatile(
        "mma.sync.aligned.m16n8k16.row.col.f32.f16.f16.f32 "
        "{%0,%1,%2,%3}, {%4,%5,%6,%7}, {%8,%9}, {%0,%1,%2,%3};\n"
        : "+f"(c[0]), "+f"(c[1]), "+f"(c[2]), "+f"(c[3])
        : "r"(a[0]), "r"(a[1]), "r"(a[2]), "r"(a[3]), "r"(b[0]), "r"(b[1]));
}

// split two fp32 into packed fp16x2 hi and fp16x2 residual
__device__ __forceinline__ void splith2(float x, float y, uint32_t &hi, uint32_t &lo) {
    __half hx = __float2half_rn(x), hy = __float2half_rn(y);
    float rx = x - __half2float(hx);
    float ry = y - __half2float(hy);
    __half lx = __float2half_rn(rx), ly = __float2half_rn(ry);
    hi = ((uint32_t)__half_as_ushort(hy) << 16) | (uint32_t)__half_as_ushort(hx);
    lo = ((uint32_t)__half_as_ushort(ly) << 16) | (uint32_t)__half_as_ushort(lx);
}
__device__ __forceinline__ void split1h(float x, uint16_t &h, uint16_t &l) {
    __half hx = __float2half_rn(x);
    h = __half_as_ushort(hx);
    l = __half_as_ushort(__float2half_rn(x - __half2float(hx)));
}

__device__ __forceinline__ uint32_t s2u(const void* p) {
    return (uint32_t)__cvta_generic_to_shared(p);
}
__device__ __forceinline__ void bulk_cp(uint32_t dst, const void* src, uint32_t bytes, uint32_t mbar) {
    asm volatile(
        "cp.async.bulk.shared::cluster.global.mbarrier::complete_tx::bytes [%0], [%1], %2, [%3];"
        :: "r"(dst), "l"(src), "r"(bytes), "r"(mbar) : "memory");
}
#define MBAR_INIT(mb, n) \
    asm volatile("mbarrier.init.shared.b64 [%0], %1;" :: "r"(mb), "r"(n) : "memory")
#define MBAR_EXPECT(mb, tx) \
    asm volatile("mbarrier.arrive.expect_tx.shared.b64 _, [%0], %1;" :: "r"(mb), "r"(tx) : "memory")
#define MBAR_ARRIVE(mb) \
    asm volatile("mbarrier.arrive.shared.b64 _, [%0];" :: "r"(mb) : "memory")
__device__ __forceinline__ void mbar_wait(uint32_t mb, uint32_t parity) {
    asm volatile(
        "{\n\t.reg .pred P;\n\t"
        "W_%=:\n\t"
        "mbarrier.try_wait.parity.acquire.cta.shared::cta.b64 P, [%0], %1, 0x989680;\n\t"
        "@P bra.uni D_%=;\n\t"
        "bra.uni W_%=;\n\t"
        "D_%=:\n\t}"
        :: "r"(mb), "r"(parity) : "memory");
}
#define HBAR(h) asm volatile("bar.sync %0, %1;" :: "r"((h) + 1), "r"(256) : "memory")

// transfer stream: [K_A nA][V_A nA][K_B nB][V_B nB]; K chunks 8KB, V chunks 16KB
__device__ __forceinline__ const uint32_t* chunk_src(
    int g, int nA, int nB, const uint32_t* kimg, const uint32_t* vimg, uint32_t* bytes) {
    if (g < nA)            { *bytes = 8192;  return kimg + (size_t)g * 2048; }
    if (g < 2 * nA)        { *bytes = 16384; return vimg + (size_t)(g - nA) * 4096; }
    if (g < 2 * nA + nB)   { *bytes = 8192;  return kimg + (size_t)(g - 2 * nA) * 2048; }
    *bytes = 16384; return vimg + (size_t)(g - 2 * nA - nB) * 4096;
}

// ---------------- pre-convert (K fp16 single + V^T fp16 hi/lo) ----------------
__global__ void conv_kernel(const float* __restrict__ kg, const float* __restrict__ vg) {
    __shared__ uint16_t th[64 * 68];
    __shared__ uint16_t tl[64 * 68];
    const int head = blockIdx.y, chunk = blockIdx.x, tid = threadIdx.x;
    const size_t srcoff = ((size_t)head * SDIM + (size_t)chunk * 64) * DDIM;

    {   // K: [key][d] fp16 single
        uint32_t* kb = g_k + (size_t)(head * 32 + chunk) * 2048;
        const float4* ksrc = (const float4*)(kg + srcoff);
        #pragma unroll
        for (int rep = 0; rep < 4; ++rep) {
            int lin = tid + rep * 256;
            int k6 = lin >> 4, d4 = (lin & 15) * 4;
            float4 v = ksrc[lin];
            __half2 h01 = __floats2half2_rn(v.x, v.y);
            __half2 h23 = __floats2half2_rn(v.z, v.w);
            uint32_t wp = (uint32_t)(k6 * 32 + (d4 >> 1)) ^ ((uint32_t)(k6 & 7) << 2);
            kb[wp]     = *(uint32_t*)&h01;
            kb[wp + 1] = *(uint32_t*)&h23;
        }
    }
    {   // V: transpose to [d][key] fp16 hi/lo
        const float4* vsrc = (const float4*)(vg + srcoff);
        #pragma unroll
        for (int rep = 0; rep < 4; ++rep) {
            int lin = tid + rep * 256;
            int key = lin >> 4, d4 = (lin & 15) * 4;
            float4 v = vsrc[lin];
            uint16_t h, l;
            split1h(v.x, h, l); th[(d4 + 0) * 68 + key] = h; tl[(d4 + 0) * 68 + key] = l;
            split1h(v.y, h, l); th[(d4 + 1) * 68 + key] = h; tl[(d4 + 1) * 68 + key] = l;
            split1h(v.z, h, l); th[(d4 + 2) * 68 + key] = h; tl[(d4 + 2) * 68 + key] = l;
            split1h(v.w, h, l); th[(d4 + 3) * 68 + key] = h; tl[(d4 + 3) * 68 + key] = l;
        }
        __syncthreads();
        uint32_t* vb = g_v + (size_t)(head * 32 + chunk) * 4096;
        #pragma unroll
        for (int rep = 0; rep < 8; ++rep) {
            int lin = tid + rep * 256;
            int d = lin >> 5, kp = lin & 31;
            uint32_t hi = (uint32_t)th[d * 68 + kp * 2] | ((uint32_t)th[d * 68 + kp * 2 + 1] << 16);
            uint32_t lo = (uint32_t)tl[d * 68 + kp * 2] | ((uint32_t)tl[d * 68 + kp * 2 + 1] << 16);
            uint32_t wp = (uint32_t)(d * 32) + ((uint32_t)kp ^ ((uint32_t)(d & 7) << 2));
            vb[wp] = hi; vb[2048 + wp] = lo;
        }
    }
}

// ---------------- fused attention: async slots, halves, fp16 2-term QK ----------------
__global__ __launch_bounds__(NTHREADS, 1)
void attn_kernel(const float* __restrict__ qg, float* __restrict__ outg,
                 float* __restrict__ attng)
{
    extern __shared__ char sm[];
    uint16_t* sc   = (uint16_t*)(sm + OFF_SC);
    uint32_t* scw  = (uint32_t*)(sm + OFF_SC);
    float*    qs   = (float*)(sm + OFF_QS);
    uint32_t* slots= (uint32_t*)(sm + OFF_SLOT);
    float*    ssum = (float*)(sm + OFF_SSUM);
    float*    sinv = (float*)(sm + OFF_SINV);

    const int bh = blockIdx.y;
    const int pr = blockIdx.x;
    const int tid = threadIdx.x, lane = tid & 31, wid = tid >> 5;
    const int w7 = wid & 7, hh = wid >> 3, rbase = hh * 16;
    const int tid_h = tid & 255;
    const int r4 = lane >> 2, l3 = lane & 3, c0 = l3 * 2;
    const uint32_t xm = (uint32_t)(lane >> 2) << 2;

    const size_t headoff = (size_t)bh * SDIM * DDIM;
    const uint32_t* kimg = g_k + (size_t)bh * 32 * 2048;
    const uint32_t* vimg = g_v + (size_t)bh * 32 * 4096;

    const int qbA = pr * TQ, qbB = (63 - pr) * TQ;
    const int nA = (qbA + TQ + 63) >> 6, nB = (qbB + TQ + 63) >> 6;
    const int T = 2 * (nA + nB);

    const uint32_t mbF = s2u(sm + OFF_MBAR);       // full[4]
    const uint32_t mbE = mbF + 32;                 // empty[4]
    if (tid == 0) {
        #pragma unroll
        for (int s = 0; s < 4; ++s) { MBAR_INIT(mbF + 8 * s, 1); MBAR_INIT(mbE + 8 * s, 16); }
    }
    __syncthreads();
    if (tid == 0) {
        #pragma unroll
        for (int j = 0; j < 3; ++j) {
            uint32_t nb;
            const uint32_t* src = chunk_src(j, nA, nB, kimg, vimg, &nb);
            MBAR_EXPECT(mbF + 8 * j, nb);
            bulk_cp(s2u(slots + j * 4096), src, nb, mbF + 8 * j);
        }
    }

    auto issue_next = [&](int g) {   // tid0: issue transfer g+3
        int j = g + 3;
        if (j >= T) return;
        int s = j & 3;
        if (j >= 4) mbar_wait(mbE + 8 * s, (uint32_t)(((j >> 2) - 1) & 1));
        uint32_t nb;
        const uint32_t* src = chunk_src(j, nA, nB, kimg, vimg, &nb);
        MBAR_EXPECT(mbF + 8 * s, nb);
        bulk_cp(s2u(slots + s * 4096), src, nb, mbF + 8 * s);
    };

    int g = 0;
    #pragma unroll 1
    for (int t = 0; t < 2; ++t) {
        const int qbase = t ? qbB : qbA;
        const int n     = t ? nB  : nA;
        const int cendC = n * 64;

        // ---- stage q rows of own half ----
        {
            int rl = tid_h >> 4, dg = (tid_h & 15) * 4;
            float4 v = *(const float4*)(qg + headoff + (size_t)(qbase + rbase + rl) * DDIM + dg);
            *(float4*)(qs + (rbase + rl) * DDIM + dg) =
                make_float4(v.x * 0.125f, v.y * 0.125f, v.z * 0.125f, v.w * 0.125f);
        }
        HBAR(hh);

        // Q A-fragments (fp16 hi/lo)
        uint32_t aqh[4][4], aql[4][4];
        #pragma unroll
        for (int ks = 0; ks < 4; ++ks) {
            const float* q0 = qs + (rbase + r4) * DDIM + ks * 16;
            const float* q1 = q0 + 8 * DDIM;
            splith2(q0[c0],     q0[c0 + 1], aqh[ks][0], aql[ks][0]);
            splith2(q1[c0],     q1[c0 + 1], aqh[ks][1], aql[ks][1]);
            splith2(q0[c0 + 8], q0[c0 + 9], aqh[ks][2], aql[ks][2]);
            splith2(q1[c0 + 8], q1[c0 + 9], aqh[ks][3], aql[ks][3]);
        }

        // ---------------- pass 1: QK (fp16 2-term) + exp + sums + sc ----------------
        float s0 = 0.f, s1 = 0.f;
        const int row0 = qbase + rbase + r4, row1 = row0 + 8;
        const int kwb  = (w7 * 8 + (lane >> 2)) * 32;

        #pragma unroll 1
        for (int c = 0; c < n; ++c, ++g) {
            if (tid == 0) issue_next(g);
            mbar_wait(mbF + 8 * (g & 3), (uint32_t)((g >> 2) & 1));

            const uint32_t* kh = slots + (g & 3) * 4096;
            float a0[4] = {0,0,0,0}, a1[4] = {0,0,0,0};
            float a2[4] = {0,0,0,0}, a3[4] = {0,0,0,0};
            #define QKS(AH, AL, KS) { \
                uint32_t i0 = kwb + (((uint32_t)((KS)*8 + l3))     ^ xm); \
                uint32_t i1 = kwb + (((uint32_t)((KS)*8 + l3 + 4)) ^ xm); \
                uint32_t bh2[2] = {kh[i0], kh[i1]}; \
                mma16816h(AH, aqh[KS], bh2); \
                mma16816h(AL, aql[KS], bh2); }
            QKS(a0, a1, 0) QKS(a2, a3, 1) QKS(a0, a1, 2) QKS(a2, a3, 3)
            #undef QKS

            __syncwarp();
            if (lane == 0) MBAR_ARRIVE(mbE + 8 * (g & 3));

            const float acc0 = (a0[0] + a1[0]) + (a2[0] + a3[0]);
            const float acc1 = (a0[1] + a1[1]) + (a2[1] + a3[1]);
            const float acc2 = (a0[2] + a1[2]) + (a2[2] + a3[2]);
            const float acc3 = (a0[3] + a1[3]) + (a2[3] + a3[3]);

            const int col = c * 64 + w7 * 8 + c0;
            float p0 = (col     <= row0) ? __expf(acc0) : 0.f;
            float p1 = (col + 1 <= row0) ? __expf(acc1) : 0.f;
            float p2 = (col     <= row1) ? __expf(acc2) : 0.f;
            float p3 = (col + 1 <= row1) ? __expf(acc3) : 0.f;
            s0 += p0 + p1;
            s1 += p2 + p3;

            __half2 h01 = __floats2half2_rn(p0, p1);
            __half2 h23 = __floats2half2_rn(p2, p3);
            scw[(rbase + r4) * SCW     + (col >> 1)] = *(uint32_t*)&h01;
            scw[(rbase + r4 + 8) * SCW + (col >> 1)] = *(uint32_t*)&h23;
        }

        // ---------------- row sums -> sinv (per half) ----------------
        s0 += __shfl_xor_sync(0xffffffffu, s0, 1);
        s0 += __shfl_xor_sync(0xffffffffu, s0, 2);
        s1 += __shfl_xor_sync(0xffffffffu, s1, 1);
        s1 += __shfl_xor_sync(0xffffffffu, s1, 2);
        if (l3 == 0) {
            ssum[(rbase + r4) * 8 + w7]     = s0;
            ssum[(rbase + r4 + 8) * 8 + w7] = s1;
        }
        HBAR(hh);
        if (tid_h < 16) {
            float s = 0.f;
            #pragma unroll
            for (int w = 0; w < 8; ++w) s += ssum[(rbase + tid_h) * 8 + w];
            sinv[rbase + tid_h] = 1.0f / s;
        }
        HBAR(hh);

        // ---------------- pass 2: PV (fp16 k16, split acc) + attn write ----------------
        float oca[4] = {0.f, 0.f, 0.f, 0.f};
        float ocb[4] = {0.f, 0.f, 0.f, 0.f};
        const int dloc = w7 * 8 + (lane >> 2);
        const int arown = rbase + (tid_h >> 4);
        const float invr = sinv[arown];
        float* arow = attng ? attng + ((size_t)bh * SDIM + qbase + arown) * SDIM : (float*)0;

        #pragma unroll 1
        for (int c = 0; c < n; ++c, ++g) {
            if (tid == 0) issue_next(g);
            mbar_wait(mbF + 8 * (g & 3), (uint32_t)((g >> 2) & 1));

            const uint32_t* vh = slots + (g & 3) * 4096;
            const int cb2 = c * 32;
            #pragma unroll
            for (int kg = 0; kg < 4; ++kg) {
                uint32_t a[4];
                a[0] = scw[(rbase + r4) * SCW     + cb2 + kg * 8 + l3];
                a[1] = scw[(rbase + r4 + 8) * SCW + cb2 + kg * 8 + l3];
                a[2] = scw[(rbase + r4) * SCW     + cb2 + kg * 8 + 4 + l3];
                a[3] = scw[(rbase + r4 + 8) * SCW + cb2 + kg * 8 + 4 + l3];
                uint32_t vi0 = (uint32_t)(dloc * 32) + (((uint32_t)(kg * 8 + l3))     ^ xm);
                uint32_t vi1 = (uint32_t)(dloc * 32) + (((uint32_t)(kg * 8 + 4 + l3)) ^ xm);
                uint32_t bh2[2] = {vh[vi0],        vh[vi1]};
                uint32_t bl2[2] = {vh[2048 + vi0], vh[2048 + vi1]};
                float* oc = (kg & 1) ? ocb : oca;
                mma16816h(oc, a, bh2);
                mma16816h(oc, a, bl2);
            }

            __syncwarp();
            if (lane == 0) MBAR_ARRIVE(mbE + 8 * (g & 3));

            if (arow) {
                const int jc = c * 64 + (tid_h & 15) * 4;
                uint2 pk = *(const uint2*)(sc + arown * SCH + jc);
                float2 fa = __half22float2(*(__half2*)&pk.x);
                float2 fb = __half22float2(*(__half2*)&pk.y);
                __stcs((float4*)(arow + jc),
                       make_float4(fa.x * invr, fa.y * invr, fb.x * invr, fb.y * invr));
            }
        }

        // attn tail zeros (own-half rows)
        if (arow) {
            for (int j = cendC + (tid_h & 15) * 4; j < SDIM; j += 64)
                __stcs((float4*)(arow + j), make_float4(0.f, 0.f, 0.f, 0.f));
        }

        // output write (warp-owned 16x8 block, own half)
        {
            const float sv0 = sinv[rbase + r4], sv1 = sinv[rbase + r4 + 8];
            float* orow = outg + headoff + (size_t)(qbase + rbase + r4) * DDIM;
            const int dc = w7 * 8 + c0;
            *(float2*)(orow + dc) =
                make_float2((oca[0] + ocb[0]) * sv0, (oca[1] + ocb[1]) * sv0);
            *(float2*)(orow + 8 * DDIM + dc) =
                make_float2((oca[2] + ocb[2]) * sv1, (oca[3] + ocb[3]) * sv1);
        }
        HBAR(hh);   // own half fully done with sc/qs before next tile overwrites
    }
}

extern "C" void kernel_launch(void* const* d_in, const int* in_sizes, int n_in,
                              void* d_out, int out_size) {
    const float* q = (const float*)d_in[0];
    const float* k = (const float*)d_in[1];
    const float* v = (const float*)d_in[2];

    float* out = (float*)d_out;
    const long long OUT_E  = 64LL * 2048 * 64;
    const long long ATTN_E = 64LL * 2048 * 2048;
    float* attn = ((long long)out_size >= OUT_E + ATTN_E) ? out + OUT_E : nullptr;

    {
        dim3 g(32, 64);
        conv_kernel<<<g, 256>>>(k, v);
    }

    cudaFuncSetAttribute(attn_kernel,
                         cudaFuncAttributeMaxDynamicSharedMemorySize, SMEM_BYTES);
    dim3 grid(32, 64);
    attn_kernel<<<grid, NTHREADS, SMEM_BYTES>>>(q, out, attn);
}

// round 12
// speedup vs baseline: 1.2866x; 1.0184x over previous
#include <cuda_runtime.h>
#include <cuda_fp16.h>
#include <cuda_bf16.h>
#include <stdint.h>

#define SDIM 2048
#define DDIM 64
#define TQ 16
#define NTHREADS 256
#define SCH 2088            // sc row stride (u16)
#define SCW 1044            // sc row stride (u32)

// smem byte offsets (105 KB total -> 2 CTAs/SM)
#define OFF_SC    0                  // 16*2088*2 = 66816
#define OFF_QS    66816              // 16*64*4 = 4096
#define OFF_SLOT  71680              // 2 slots * 16384 = 32768
#define OFF_SSUM  104448             // 16*8*4 = 512
#define OFF_SINV  104960             // 64
#define OFF_MBAR  105024             // full[2], empty[2]
#define SMEM_BYTES 105472

// pre-converted chunk-blocked swizzled images
__device__ __align__(16) uint32_t g_k[64u * 32u * 2048u];        // fp16 single, [key][d]
__device__ __align__(16) uint32_t g_v[64u * 32u * 2u * 2048u];   // fp16 hi/lo, [d][key]

__device__ __forceinline__ void mma16816h(float c[4], const uint32_t a[4], const uint32_t b[2]) {
    asm volatile(
        "mma.sync.aligned.m16n8k16.row.col.f32.f16.f16.f32 "
        "{%0,%1,%2,%3}, {%4,%5,%6,%7}, {%8,%9}, {%0,%1,%2,%3};\n"
        : "+f"(c[0]), "+f"(c[1]), "+f"(c[2]), "+f"(c[3])
        : "r"(a[0]), "r"(a[1]), "r"(a[2]), "r"(a[3]), "r"(b[0]), "r"(b[1]));
}

__device__ __forceinline__ void splith2(float x, float y, uint32_t &hi, uint32_t &lo) {
    __half hx = __float2half_rn(x), hy = __float2half_rn(y);
    float rx = x - __half2float(hx);
    float ry = y - __half2float(hy);
    __half lx = __float2half_rn(rx), ly = __float2half_rn(ry);
    hi = ((uint32_t)__half_as_ushort(hy) << 16) | (uint32_t)__half_as_ushort(hx);
    lo = ((uint32_t)__half_as_ushort(ly) << 16) | (uint32_t)__half_as_ushort(lx);
}
__device__ __forceinline__ void split1h(float x, uint16_t &h, uint16_t &l) {
    __half hx = __float2half_rn(x);
    h = __half_as_ushort(hx);
    l = __half_as_ushort(__float2half_rn(x - __half2float(hx)));
}

__device__ __forceinline__ uint32_t s2u(const void* p) {
    return (uint32_t)__cvta_generic_to_shared(p);
}
__device__ __forceinline__ void bulk_cp(uint32_t dst, const void* src, uint32_t bytes, uint32_t mbar) {
    asm volatile(
        "cp.async.bulk.shared::cluster.global.mbarrier::complete_tx::bytes [%0], [%1], %2, [%3];"
        :: "r"(dst), "l"(src), "r"(bytes), "r"(mbar) : "memory");
}
#define MBAR_INIT(mb, n) \
    asm volatile("mbarrier.init.shared.b64 [%0], %1;" :: "r"(mb), "r"(n) : "memory")
#define MBAR_EXPECT(mb, tx) \
    asm volatile("mbarrier.arrive.expect_tx.shared.b64 _, [%0], %1;" :: "r"(mb), "r"(tx) : "memory")
#define MBAR_ARRIVE(mb) \
    asm volatile("mbarrier.arrive.shared.b64 _, [%0];" :: "r"(mb) : "memory")
__device__ __forceinline__ void mbar_wait(uint32_t mb, uint32_t parity) {
    asm volatile(
        "{\n\t.reg .pred P;\n\t"
        "W_%=:\n\t"
        "mbarrier.try_wait.parity.acquire.cta.shared::cta.b64 P, [%0], %1, 0x989680;\n\t"
        "@P bra.uni D_%=;\n\t"
        "bra.uni W_%=;\n\t"
        "D_%=:\n\t}"
        :: "r"(mb), "r"(parity) : "memory");
}

// transfer stream: [K_A nA][V_A nA][K_B nB][V_B nB]; K chunks 8KB, V chunks 16KB
__device__ __forceinline__ const uint32_t* chunk_src(
    int g, int nA, int nB, const uint32_t* kimg, const uint32_t* vimg, uint32_t* bytes) {
    if (g < nA)            { *bytes = 8192;  return kimg + (size_t)g * 2048; }
    if (g < 2 * nA)        { *bytes = 16384; return vimg + (size_t)(g - nA) * 4096; }
    if (g < 2 * nA + nB)   { *bytes = 8192;  return kimg + (size_t)(g - 2 * nA) * 2048; }
    *bytes = 16384; return vimg + (size_t)(g - 2 * nA - nB) * 4096;
}

// ---------------- pre-convert (K fp16 single + V^T fp16 hi/lo) ----------------
__global__ void conv_kernel(const float* __restrict__ kg, const float* __restrict__ vg) {
    __shared__ uint16_t th[64 * 68];
    __shared__ uint16_t tl[64 * 68];
    const int head = blockIdx.y, chunk = blockIdx.x, tid = threadIdx.x;
    const size_t srcoff = ((size_t)head * SDIM + (size_t)chunk * 64) * DDIM;

    {   // K: [key][d] fp16 single
        uint32_t* kb = g_k + (size_t)(head * 32 + chunk) * 2048;
        const float4* ksrc = (const float4*)(kg + srcoff);
        #pragma unroll
        for (int rep = 0; rep < 4; ++rep) {
            int lin = tid + rep * 256;
            int k6 = lin >> 4, d4 = (lin & 15) * 4;
            float4 v = ksrc[lin];
            __half2 h01 = __floats2half2_rn(v.x, v.y);
            __half2 h23 = __floats2half2_rn(v.z, v.w);
            uint32_t wp = (uint32_t)(k6 * 32 + (d4 >> 1)) ^ ((uint32_t)(k6 & 7) << 2);
            kb[wp]     = *(uint32_t*)&h01;
            kb[wp + 1] = *(uint32_t*)&h23;
        }
    }
    {   // V: transpose to [d][key] fp16 hi/lo
        const float4* vsrc = (const float4*)(vg + srcoff);
        #pragma unroll
        for (int rep = 0; rep < 4; ++rep) {
            int lin = tid + rep * 256;
            int key = lin >> 4, d4 = (lin & 15) * 4;
            float4 v = vsrc[lin];
            uint16_t h, l;
            split1h(v.x, h, l); th[(d4 + 0) * 68 + key] = h; tl[(d4 + 0) * 68 + key] = l;
            split1h(v.y, h, l); th[(d4 + 1) * 68 + key] = h; tl[(d4 + 1) * 68 + key] = l;
            split1h(v.z, h, l); th[(d4 + 2) * 68 + key] = h; tl[(d4 + 2) * 68 + key] = l;
            split1h(v.w, h, l); th[(d4 + 3) * 68 + key] = h; tl[(d4 + 3) * 68 + key] = l;
        }
        __syncthreads();
        uint32_t* vb = g_v + (size_t)(head * 32 + chunk) * 4096;
        #pragma unroll
        for (int rep = 0; rep < 8; ++rep) {
            int lin = tid + rep * 256;
            int d = lin >> 5, kp = lin & 31;
            uint32_t hi = (uint32_t)th[d * 68 + kp * 2] | ((uint32_t)th[d * 68 + kp * 2 + 1] << 16);
            uint32_t lo = (uint32_t)tl[d * 68 + kp * 2] | ((uint32_t)tl[d * 68 + kp * 2 + 1] << 16);
            uint32_t wp = (uint32_t)(d * 32) + ((uint32_t)kp ^ ((uint32_t)(d & 7) << 2));
            vb[wp] = hi; vb[2048 + wp] = lo;
        }
    }
}

// ---------------- fused attention: TQ=16, 2 CTAs/SM ----------------
__global__ __launch_bounds__(NTHREADS, 2)
void attn_kernel(const float* __restrict__ qg, float* __restrict__ outg,
                 float* __restrict__ attng)
{
    extern __shared__ char sm[];
    uint16_t* sc   = (uint16_t*)(sm + OFF_SC);
    uint32_t* scw  = (uint32_t*)(sm + OFF_SC);
    float*    qs   = (float*)(sm + OFF_QS);
    uint32_t* slots= (uint32_t*)(sm + OFF_SLOT);
    float*    ssum = (float*)(sm + OFF_SSUM);
    float*    sinv = (float*)(sm + OFF_SINV);

    const int bh = blockIdx.y;
    const int pr = blockIdx.x;                  // pair id, 0..63
    const int tid = threadIdx.x, lane = tid & 31, wid = tid >> 5;   // 8 warps
    const int r4 = lane >> 2, l3 = lane & 3, c0 = l3 * 2;
    const uint32_t xm = (uint32_t)(lane >> 2) << 2;

    const size_t headoff = (size_t)bh * SDIM * DDIM;
    const uint32_t* kimg = g_k + (size_t)bh * 32 * 2048;
    const uint32_t* vimg = g_v + (size_t)bh * 32 * 4096;

    const int tA = pr, tB = 127 - pr;           // 16-row tiles
    const int qbA = tA * TQ, qbB = tB * TQ;
    const int nA = (qbA + TQ + 63) >> 6, nB = (qbB + TQ + 63) >> 6;   // nA+nB == 33
    const int T = 2 * (nA + nB);

    const uint32_t mbF = s2u(sm + OFF_MBAR);    // full[2]
    const uint32_t mbE = mbF + 16;              // empty[2]
    if (tid == 0) {
        #pragma unroll
        for (int s = 0; s < 2; ++s) { MBAR_INIT(mbF + 8 * s, 1); MBAR_INIT(mbE + 8 * s, 8); }
    }
    __syncthreads();
    if (tid == 0) {
        #pragma unroll
        for (int j = 0; j < 2; ++j) {
            uint32_t nb;
            const uint32_t* src = chunk_src(j, nA, nB, kimg, vimg, &nb);
            MBAR_EXPECT(mbF + 8 * j, nb);
            bulk_cp(s2u(slots + j * 4096), src, nb, mbF + 8 * j);
        }
    }

    // tid0: at top of iteration g, issue transfer g+1 (slot freed at end of iter g-1)
    auto issue_next = [&](int g) {
        int j = g + 1;
        if (j >= T || j < 2) return;
        int s = j & 1;
        mbar_wait(mbE + 8 * s, (uint32_t)(((j >> 1) - 1) & 1));
        uint32_t nb;
        const uint32_t* src = chunk_src(j, nA, nB, kimg, vimg, &nb);
        MBAR_EXPECT(mbF + 8 * s, nb);
        bulk_cp(s2u(slots + s * 4096), src, nb, mbF + 8 * s);
    };

    int g = 0;
    #pragma unroll 1
    for (int t = 0; t < 2; ++t) {
        const int qbase = t ? qbB : qbA;
        const int n     = t ? nB  : nA;
        const int cendC = n * 64;

        // ---- stage q tile (256 threads x float4 = 16x64) ----
        {
            int rl = tid >> 4, dg = (tid & 15) * 4;
            float4 v = *(const float4*)(qg + headoff + (size_t)(qbase + rl) * DDIM + dg);
            *(float4*)(qs + rl * DDIM + dg) =
                make_float4(v.x * 0.125f, v.y * 0.125f, v.z * 0.125f, v.w * 0.125f);
        }
        __syncthreads();

        // Q A-fragments (fp16 hi/lo)
        uint32_t aqh[4][4], aql[4][4];
        #pragma unroll
        for (int ks = 0; ks < 4; ++ks) {
            const float* q0 = qs + r4 * DDIM + ks * 16;
            const float* q1 = q0 + 8 * DDIM;
            splith2(q0[c0],     q0[c0 + 1], aqh[ks][0], aql[ks][0]);
            splith2(q1[c0],     q1[c0 + 1], aqh[ks][1], aql[ks][1]);
            splith2(q0[c0 + 8], q0[c0 + 9], aqh[ks][2], aql[ks][2]);
            splith2(q1[c0 + 8], q1[c0 + 9], aqh[ks][3], aql[ks][3]);
        }

        // ---------------- pass 1: QK (fp16 2-term) + exp + sums + sc ----------------
        float s0 = 0.f, s1 = 0.f;
        const int row0 = qbase + r4, row1 = row0 + 8;
        const int kwb  = (wid * 8 + (lane >> 2)) * 32;

        #pragma unroll 1
        for (int c = 0; c < n; ++c, ++g) {
            if (tid == 0) issue_next(g);
            mbar_wait(mbF + 8 * (g & 1), (uint32_t)((g >> 1) & 1));

            const uint32_t* kh = slots + (g & 1) * 4096;
            float a0[4] = {0,0,0,0}, a1[4] = {0,0,0,0};
            float a2[4] = {0,0,0,0}, a3[4] = {0,0,0,0};
            #define QKS(AH, AL, KS) { \
                uint32_t i0 = kwb + (((uint32_t)((KS)*8 + l3))     ^ xm); \
                uint32_t i1 = kwb + (((uint32_t)((KS)*8 + l3 + 4)) ^ xm); \
                uint32_t bh2[2] = {kh[i0], kh[i1]}; \
                mma16816h(AH, aqh[KS], bh2); \
                mma16816h(AL, aql[KS], bh2); }
            QKS(a0, a1, 0) QKS(a2, a3, 1) QKS(a0, a1, 2) QKS(a2, a3, 3)
            #undef QKS

            __syncwarp();
            if (lane == 0) MBAR_ARRIVE(mbE + 8 * (g & 1));

            const float acc0 = (a0[0] + a1[0]) + (a2[0] + a3[0]);
            const float acc1 = (a0[1] + a1[1]) + (a2[1] + a3[1]);
            const float acc2 = (a0[2] + a1[2]) + (a2[2] + a3[2]);
            const float acc3 = (a0[3] + a1[3]) + (a2[3] + a3[3]);

            const int col = c * 64 + wid * 8 + c0;
            float p0 = (col     <= row0) ? __expf(acc0) : 0.f;
            float p1 = (col + 1 <= row0) ? __expf(acc1) : 0.f;
            float p2 = (col     <= row1) ? __expf(acc2) : 0.f;
            float p3 = (col + 1 <= row1) ? __expf(acc3) : 0.f;
            s0 += p0 + p1;
            s1 += p2 + p3;

            __half2 h01 = __floats2half2_rn(p0, p1);
            __half2 h23 = __floats2half2_rn(p2, p3);
            scw[r4 * SCW       + (col >> 1)] = *(uint32_t*)&h01;
            scw[(r4 + 8) * SCW + (col >> 1)] = *(uint32_t*)&h23;
        }

        // ---------------- row sums -> sinv ----------------
        s0 += __shfl_xor_sync(0xffffffffu, s0, 1);
        s0 += __shfl_xor_sync(0xffffffffu, s0, 2);
        s1 += __shfl_xor_sync(0xffffffffu, s1, 1);
        s1 += __shfl_xor_sync(0xffffffffu, s1, 2);
        if (l3 == 0) {
            ssum[r4 * 8 + wid]       = s0;
            ssum[(r4 + 8) * 8 + wid] = s1;
        }
        __syncthreads();
        if (tid < TQ) {
            float s = 0.f;
            #pragma unroll
            for (int w = 0; w < 8; ++w) s += ssum[tid * 8 + w];
            sinv[tid] = 1.0f / s;
        }
        __syncthreads();

        // ---------------- pass 2: PV (fp16 k16, split acc) + attn write ----------------
        float oca[4] = {0.f, 0.f, 0.f, 0.f};
        float ocb[4] = {0.f, 0.f, 0.f, 0.f};
        const int dloc = wid * 8 + (lane >> 2);
        const int arown = tid >> 4;
        const float invr = sinv[arown];
        float* arow = attng ? attng + ((size_t)bh * SDIM + qbase + arown) * SDIM : (float*)0;

        #pragma unroll 1
        for (int c = 0; c < n; ++c, ++g) {
            if (tid == 0) issue_next(g);
            mbar_wait(mbF + 8 * (g & 1), (uint32_t)((g >> 1) & 1));

            const uint32_t* vh = slots + (g & 1) * 4096;
            const int cb2 = c * 32;
            #pragma unroll
            for (int kg = 0; kg < 4; ++kg) {
                uint32_t a[4];
                a[0] = scw[r4 * SCW       + cb2 + kg * 8 + l3];
                a[1] = scw[(r4 + 8) * SCW + cb2 + kg * 8 + l3];
                a[2] = scw[r4 * SCW       + cb2 + kg * 8 + 4 + l3];
                a[3] = scw[(r4 + 8) * SCW + cb2 + kg * 8 + 4 + l3];
                uint32_t vi0 = (uint32_t)(dloc * 32) + (((uint32_t)(kg * 8 + l3))     ^ xm);
                uint32_t vi1 = (uint32_t)(dloc * 32) + (((uint32_t)(kg * 8 + 4 + l3)) ^ xm);
                uint32_t bh2[2] = {vh[vi0],        vh[vi1]};
                uint32_t bl2[2] = {vh[2048 + vi0], vh[2048 + vi1]};
                float* oc = (kg & 1) ? ocb : oca;
                mma16816h(oc, a, bh2);
                mma16816h(oc, a, bl2);
            }

            __syncwarp();
            if (lane == 0) MBAR_ARRIVE(mbE + 8 * (g & 1));

            if (arow) {
                const int jc = c * 64 + (tid & 15) * 4;
                uint2 pk = *(const uint2*)(sc + arown * SCH + jc);
                float2 fa = __half22float2(*(__half2*)&pk.x);
                float2 fb = __half22float2(*(__half2*)&pk.y);
                __stcs((float4*)(arow + jc),
                       make_float4(fa.x * invr, fa.y * invr, fb.x * invr, fb.y * invr));
            }
        }

        // attn tail zeros
        if (arow) {
            for (int j = cendC + (tid & 15) * 4; j < SDIM; j += 64)
                __stcs((float4*)(arow + j), make_float4(0.f, 0.f, 0.f, 0.f));
        }

        // output write (warp-owned 16x8 block)
        {
            const float sv0 = sinv[r4], sv1 = sinv[r4 + 8];
            float* orow = outg + headoff + (size_t)(qbase + r4) * DDIM;
            const int dc = wid * 8 + c0;
            *(float2*)(orow + dc) =
                make_float2((oca[0] + ocb[0]) * sv0, (oca[1] + ocb[1]) * sv0);
            *(float2*)(orow + 8 * DDIM + dc) =
                make_float2((oca[2] + ocb[2]) * sv1, (oca[3] + ocb[3]) * sv1);
        }
        __syncthreads();   // sc/qs reuse guard before next tile
    }
}

extern "C" void kernel_launch(void* const* d_in, const int* in_sizes, int n_in,
                              void* d_out, int out_size) {
    const float* q = (const float*)d_in[0];
    const float* k = (const float*)d_in[1];
    const float* v = (const float*)d_in[2];

    float* out = (float*)d_out;
    const long long OUT_E  = 64LL * 2048 * 64;
    const long long ATTN_E = 64LL * 2048 * 2048;
    float* attn = ((long long)out_size >= OUT_E + ATTN_E) ? out + OUT_E : nullptr;

    {
        dim3 g(32, 64);
        conv_kernel<<<g, 256>>>(k, v);
    }

    cudaFuncSetAttribute(attn_kernel,
                         cudaFuncAttributeMaxDynamicSharedMemorySize, SMEM_BYTES);
    dim3 grid(64, 64);   // 64 balanced tile-pairs x 64 heads = 4096 CTAs
    attn_kernel<<<grid, NTHREADS, SMEM_BYTES>>>(q, out, attn);
}

// round 13
// speedup vs baseline: 1.7036x; 1.3241x over previous
#include <cuda_runtime.h>
#include <cuda_fp16.h>
#include <stdint.h>

#define SDIM 2048
#define DDIM 64
#define TQ 16
#define NTHREADS 256
#define SCH 2088            // sc row stride (u16)
#define SCW 1044            // sc row stride (u32)

// smem byte offsets (70 KB total -> 3 CTAs/SM)
#define OFF_SC    0                  // 16*2088*2 = 66816
#define OFF_QS    66816              // 16*64*4 = 4096
#define OFF_SSUM  70912              // 16*8*4 = 512
#define OFF_SINV  71424              // 64
#define SMEM_BYTES 71680

// pre-packed fragment images (coalesced per-warp LDG)
// K: u32[head][chunk][warp w][ks][r][l3][elem] ; QK B-frag = uint2 LDG.64
__device__ __align__(16) uint32_t g_k2[64u * 32u * 2048u];
// V: uint4[head][chunk][kg][d][l3] = {vhi kp0, vhi kp1, vlo kp0, vlo kp1} ; LDG.128
__device__ __align__(16) uint4    g_v4[64u * 32u * 1024u];

__device__ __forceinline__ void mma16816h(float c[4], const uint32_t a[4], const uint32_t b[2]) {
    asm volatile(
        "mma.sync.aligned.m16n8k16.row.col.f32.f16.f16.f32 "
        "{%0,%1,%2,%3}, {%4,%5,%6,%7}, {%8,%9}, {%0,%1,%2,%3};\n"
        : "+f"(c[0]), "+f"(c[1]), "+f"(c[2]), "+f"(c[3])
        : "r"(a[0]), "r"(a[1]), "r"(a[2]), "r"(a[3]), "r"(b[0]), "r"(b[1]));
}

__device__ __forceinline__ void splith2(float x, float y, uint32_t &hi, uint32_t &lo) {
    __half hx = __float2half_rn(x), hy = __float2half_rn(y);
    float rx = x - __half2float(hx);
    float ry = y - __half2float(hy);
    __half lx = __float2half_rn(rx), ly = __float2half_rn(ry);
    hi = ((uint32_t)__half_as_ushort(hy) << 16) | (uint32_t)__half_as_ushort(hx);
    lo = ((uint32_t)__half_as_ushort(ly) << 16) | (uint32_t)__half_as_ushort(lx);
}
__device__ __forceinline__ void split1h(float x, uint16_t &h, uint16_t &l) {
    __half hx = __float2half_rn(x);
    h = __half_as_ushort(hx);
    l = __half_as_ushort(__float2half_rn(x - __half2float(hx)));
}

// ---------------- pre-convert: K and V^T into fragment images ----------------
__global__ void conv_kernel(const float* __restrict__ kg, const float* __restrict__ vg) {
    __shared__ uint16_t th[64 * 68];
    __shared__ uint16_t tl[64 * 68];
    const int head = blockIdx.y, chunk = blockIdx.x, tid = threadIdx.x;
    const size_t srcoff = ((size_t)head * SDIM + (size_t)chunk * 64) * DDIM;

    {   // K -> fragment image (fp16 single)
        uint32_t* kb = g_k2 + (size_t)(head * 32 + chunk) * 2048;
        const float4* ksrc = (const float4*)(kg + srcoff);
        #pragma unroll
        for (int rep = 0; rep < 4; ++rep) {
            int lin = tid + rep * 256;           // 1024 float4 (64 keys x 16)
            int k6 = lin >> 4, d4 = (lin & 15) * 4;
            float4 v = ksrc[lin];
            __half2 h01 = __floats2half2_rn(v.x, v.y);
            __half2 h23 = __floats2half2_rn(v.z, v.w);
            int w = k6 >> 3, r = k6 & 7;
            int j0 = d4 >> 1, j1 = j0 + 1;       // 32-bit word indices within key row
            // word j -> u32 pos = (((w*4 + (j>>3))*8 + r)*4 + (j&3))*2 + ((j>>2)&1)
            int p0 = (((w * 4 + (j0 >> 3)) * 8 + r) * 4 + (j0 & 3)) * 2 + ((j0 >> 2) & 1);
            int p1 = (((w * 4 + (j1 >> 3)) * 8 + r) * 4 + (j1 & 3)) * 2 + ((j1 >> 2) & 1);
            kb[p0] = *(uint32_t*)&h01;
            kb[p1] = *(uint32_t*)&h23;
        }
    }
    {   // V -> transpose [d][key] fp16 hi/lo via smem, then fragment image
        const float4* vsrc = (const float4*)(vg + srcoff);
        #pragma unroll
        for (int rep = 0; rep < 4; ++rep) {
            int lin = tid + rep * 256;
            int key = lin >> 4, d4 = (lin & 15) * 4;
            float4 v = vsrc[lin];
            uint16_t h, l;
            split1h(v.x, h, l); th[(d4 + 0) * 68 + key] = h; tl[(d4 + 0) * 68 + key] = l;
            split1h(v.y, h, l); th[(d4 + 1) * 68 + key] = h; tl[(d4 + 1) * 68 + key] = l;
            split1h(v.z, h, l); th[(d4 + 2) * 68 + key] = h; tl[(d4 + 2) * 68 + key] = l;
            split1h(v.w, h, l); th[(d4 + 3) * 68 + key] = h; tl[(d4 + 3) * 68 + key] = l;
        }
        __syncthreads();
        uint4* vb = g_v4 + (size_t)(head * 32 + chunk) * 1024;
        #pragma unroll
        for (int rep = 0; rep < 4; ++rep) {
            int lin = tid + rep * 256;           // 1024 uint4
            int l3 = lin & 3, d = (lin >> 2) & 63, kgrp = lin >> 8;
            int kp0 = kgrp * 8 + l3, kp1 = kp0 + 4;
            uint32_t h0 = (uint32_t)th[d * 68 + 2 * kp0] | ((uint32_t)th[d * 68 + 2 * kp0 + 1] << 16);
            uint32_t h1 = (uint32_t)th[d * 68 + 2 * kp1] | ((uint32_t)th[d * 68 + 2 * kp1 + 1] << 16);
            uint32_t l0 = (uint32_t)tl[d * 68 + 2 * kp0] | ((uint32_t)tl[d * 68 + 2 * kp0 + 1] << 16);
            uint32_t l1 = (uint32_t)tl[d * 68 + 2 * kp1] | ((uint32_t)tl[d * 68 + 2 * kp1 + 1] << 16);
            vb[(kgrp * 64 + d) * 4 + l3] = make_uint4(h0, h1, l0, l1);
        }
    }
}

// ---------------- fused attention: LDG fragments, 3 CTAs/SM ----------------
__global__ __launch_bounds__(NTHREADS, 3)
void attn_kernel(const float* __restrict__ qg, float* __restrict__ outg,
                 float* __restrict__ attng)
{
    extern __shared__ char sm[];
    uint16_t* sc   = (uint16_t*)(sm + OFF_SC);
    uint32_t* scw  = (uint32_t*)(sm + OFF_SC);
    float*    qs   = (float*)(sm + OFF_QS);
    float*    ssum = (float*)(sm + OFF_SSUM);
    float*    sinv = (float*)(sm + OFF_SINV);

    const int bh = blockIdx.y;
    const int pr = blockIdx.x;                  // pair id, 0..63
    const int tid = threadIdx.x, lane = tid & 31, wid = tid >> 5;
    const int r4 = lane >> 2, l3 = lane & 3, c0 = l3 * 2;

    const size_t headoff = (size_t)bh * SDIM * DDIM;
    const uint2* kimg = (const uint2*)g_k2 + (size_t)bh * 32 * 1024;
    const uint4* vimg = g_v4 + (size_t)bh * 32 * 1024;

    const int qbA = pr * TQ, qbB = (127 - pr) * TQ;
    const int nA = (qbA + TQ + 63) >> 6, nB = (qbB + TQ + 63) >> 6;   // nA+nB == 33

    #pragma unroll 1
    for (int t = 0; t < 2; ++t) {
        const int qbase = t ? qbB : qbA;
        const int n     = t ? nB  : nA;
        const int cendC = n * 64;

        // ---- stage q tile ----
        {
            int rl = tid >> 4, dg = (tid & 15) * 4;
            float4 v = *(const float4*)(qg + headoff + (size_t)(qbase + rl) * DDIM + dg);
            *(float4*)(qs + rl * DDIM + dg) =
                make_float4(v.x * 0.125f, v.y * 0.125f, v.z * 0.125f, v.w * 0.125f);
        }
        __syncthreads();

        // Q A-fragments (fp16 hi/lo)
        uint32_t aqh[4][4], aql[4][4];
        #pragma unroll
        for (int ks = 0; ks < 4; ++ks) {
            const float* q0 = qs + r4 * DDIM + ks * 16;
            const float* q1 = q0 + 8 * DDIM;
            splith2(q0[c0],     q0[c0 + 1], aqh[ks][0], aql[ks][0]);
            splith2(q1[c0],     q1[c0 + 1], aqh[ks][1], aql[ks][1]);
            splith2(q0[c0 + 8], q0[c0 + 9], aqh[ks][2], aql[ks][2]);
            splith2(q1[c0 + 8], q1[c0 + 9], aqh[ks][3], aql[ks][3]);
        }
        __syncthreads();   // qs safe to overwrite? (not overwritten until next tile's stage; guard there)

        // ---------------- pass 1: QK (fp16 2-term) + exp + sums + sc ----------------
        float s0 = 0.f, s1 = 0.f;
        const int row0 = qbase + r4, row1 = row0 + 8;
        const int kidx = (wid << 7) + (r4 << 2) + l3;   // (wid*4+ks)*32 + r*4 + l3, ks=0 base

        uint2 kf[4];
        #pragma unroll
        for (int ks = 0; ks < 4; ++ks) kf[ks] = kimg[kidx + (ks << 5)];

        #pragma unroll 1
        for (int c = 0; c < n; ++c) {
            uint2 kn[4];
            if (c + 1 < n) {
                const uint2* kc = kimg + (size_t)(c + 1) * 1024;
                #pragma unroll
                for (int ks = 0; ks < 4; ++ks) kn[ks] = kc[kidx + (ks << 5)];
            }

            float a0[4] = {0,0,0,0}, a1[4] = {0,0,0,0};
            float a2[4] = {0,0,0,0}, a3[4] = {0,0,0,0};
            #define QKS(AH, AL, KS) { \
                uint32_t bh2[2] = {kf[KS].x, kf[KS].y}; \
                mma16816h(AH, aqh[KS], bh2); \
                mma16816h(AL, aql[KS], bh2); }
            QKS(a0, a1, 0) QKS(a2, a3, 1) QKS(a0, a1, 2) QKS(a2, a3, 3)
            #undef QKS

            const float acc0 = (a0[0] + a1[0]) + (a2[0] + a3[0]);
            const float acc1 = (a0[1] + a1[1]) + (a2[1] + a3[1]);
            const float acc2 = (a0[2] + a1[2]) + (a2[2] + a3[2]);
            const float acc3 = (a0[3] + a1[3]) + (a2[3] + a3[3]);

            const int col = c * 64 + wid * 8 + c0;
            float p0 = (col     <= row0) ? __expf(acc0) : 0.f;
            float p1 = (col + 1 <= row0) ? __expf(acc1) : 0.f;
            float p2 = (col     <= row1) ? __expf(acc2) : 0.f;
            float p3 = (col + 1 <= row1) ? __expf(acc3) : 0.f;
            s0 += p0 + p1;
            s1 += p2 + p3;

            __half2 h01 = __floats2half2_rn(p0, p1);
            __half2 h23 = __floats2half2_rn(p2, p3);
            scw[r4 * SCW       + (col >> 1)] = *(uint32_t*)&h01;
            scw[(r4 + 8) * SCW + (col >> 1)] = *(uint32_t*)&h23;

            #pragma unroll
            for (int ks = 0; ks < 4; ++ks) kf[ks] = kn[ks];
        }

        // ---------------- row sums -> sinv ----------------
        s0 += __shfl_xor_sync(0xffffffffu, s0, 1);
        s0 += __shfl_xor_sync(0xffffffffu, s0, 2);
        s1 += __shfl_xor_sync(0xffffffffu, s1, 1);
        s1 += __shfl_xor_sync(0xffffffffu, s1, 2);
        if (l3 == 0) {
            ssum[r4 * 8 + wid]       = s0;
            ssum[(r4 + 8) * 8 + wid] = s1;
        }
        __syncthreads();
        if (tid < TQ) {
            float s = 0.f;
            #pragma unroll
            for (int w = 0; w < 8; ++w) s += ssum[tid * 8 + w];
            sinv[tid] = 1.0f / s;
        }
        __syncthreads();

        // ---------------- pass 2: PV (fp16 k16, split acc) + attn write ----------------
        float oca[4] = {0.f, 0.f, 0.f, 0.f};
        float ocb[4] = {0.f, 0.f, 0.f, 0.f};
        const int dloc = wid * 8 + r4;
        const int vidx = (dloc << 2) + l3;
        const int arown = tid >> 4;
        const float invr = sinv[arown];
        float* arow = attng ? attng + ((size_t)bh * SDIM + qbase + arown) * SDIM : (float*)0;

        #pragma unroll 1
        for (int c = 0; c < n; ++c) {
            const uint4* vc = vimg + (size_t)c * 1024;
            uint4 vv0 = vc[vidx];
            uint4 vv1 = vc[vidx + 256];
            uint4 vv2 = vc[vidx + 512];
            uint4 vv3 = vc[vidx + 768];

            const int cb2 = c * 32;
            #define PVS(OC, VV, KG) { \
                uint32_t a[4]; \
                a[0] = scw[r4 * SCW       + cb2 + (KG) * 8 + l3]; \
                a[1] = scw[(r4 + 8) * SCW + cb2 + (KG) * 8 + l3]; \
                a[2] = scw[r4 * SCW       + cb2 + (KG) * 8 + 4 + l3]; \
                a[3] = scw[(r4 + 8) * SCW + cb2 + (KG) * 8 + 4 + l3]; \
                uint32_t bh2[2] = {VV.x, VV.y}; \
                uint32_t bl2[2] = {VV.z, VV.w}; \
                mma16816h(OC, a, bh2); \
                mma16816h(OC, a, bl2); }
            PVS(oca, vv0, 0) PVS(ocb, vv1, 1) PVS(oca, vv2, 2) PVS(ocb, vv3, 3)
            #undef PVS

            if (arow) {
                const int jc = c * 64 + (tid & 15) * 4;
                uint2 pk = *(const uint2*)(sc + arown * SCH + jc);
                float2 fa = __half22float2(*(__half2*)&pk.x);
                float2 fb = __half22float2(*(__half2*)&pk.y);
                __stcs((float4*)(arow + jc),
                       make_float4(fa.x * invr, fa.y * invr, fb.x * invr, fb.y * invr));
            }
        }

        // attn tail zeros
        if (arow) {
            for (int j = cendC + (tid & 15) * 4; j < SDIM; j += 64)
                __stcs((float4*)(arow + j), make_float4(0.f, 0.f, 0.f, 0.f));
        }

        // output write (warp-owned 16x8 block)
        {
            const float sv0 = sinv[r4], sv1 = sinv[r4 + 8];
            float* orow = outg + headoff + (size_t)(qbase + r4) * DDIM;
            const int dc = wid * 8 + c0;
            *(float2*)(orow + dc) =
                make_float2((oca[0] + ocb[0]) * sv0, (oca[1] + ocb[1]) * sv0);
            *(float2*)(orow + 8 * DDIM + dc) =
                make_float2((oca[2] + ocb[2]) * sv1, (oca[3] + ocb[3]) * sv1);
        }
        __syncthreads();   // sc/qs reuse guard before next tile
    }
}

extern "C" void kernel_launch(void* const* d_in, const int* in_sizes, int n_in,
                              void* d_out, int out_size) {
    const float* q = (const float*)d_in[0];
    const float* k = (const float*)d_in[1];
    const float* v = (const float*)d_in[2];

    float* out = (float*)d_out;
    const long long OUT_E  = 64LL * 2048 * 64;
    const long long ATTN_E = 64LL * 2048 * 2048;
    float* attn = ((long long)out_size >= OUT_E + ATTN_E) ? out + OUT_E : nullptr;

    {
        dim3 g(32, 64);
        conv_kernel<<<g, 256>>>(k, v);
    }

    cudaFuncSetAttribute(attn_kernel,
                         cudaFuncAttributeMaxDynamicSharedMemorySize, SMEM_BYTES);
    dim3 grid(64, 64);   // 64 balanced tile-pairs x 64 heads = 4096 CTAs
    attn_kernel<<<grid, NTHREADS, SMEM_BYTES>>>(q, out, attn);
}